// round 2
// baseline (speedup 1.0000x reference)
#include <cuda_runtime.h>
#include <math.h>

#define NB   8
#define C1   256
#define C2   256
#define CM   128
#define HH   56
#define WW   56
#define HW   3136
#define NPIX (NB*HW)      // 25088
#define GG   4
#define GC   32
#define EPSS 1e-5f
#define KCONV 2304
#define NOM  108          // 72 offsets + 36 mask logits

// scratch (device globals: allocation-free rule)
__device__ float g_h [NPIX*CM];
__device__ float g_t [NPIX*CM];
__device__ float g_v [NPIX*CM];
__device__ float g_om[NPIX*NOM];
__device__ float g_o [NPIX*CM];

__device__ __forceinline__ float siluf(float v){ return v / (1.f + expf(-v)); }

// ---------------------------------------------------------------------------
// Kernel 1: 3x3 conv (C1=256 -> CM=128) + BN + SiLU, implicit GEMM.
// M tile 64 (pixels), N tile 128 (all out channels), K=2304, BK=16.
// 128 threads, 8x8 microtile.
// ---------------------------------------------------------------------------
__global__ __launch_bounds__(128) void conv1_bn_silu(
    const float* __restrict__ x, const float* __restrict__ w,
    const float* __restrict__ bg, const float* __restrict__ bb,
    const float* __restrict__ bm, const float* __restrict__ bv)
{
    __shared__ __align__(16) float As[16*68];
    __shared__ __align__(16) float Bs[16*132];
    const int t  = threadIdx.x;
    const int m0 = blockIdx.x * 64;

    // A (im2col) load mapping: fixed pixel per thread, k varies
    const int am  = t & 63;
    const int ak0 = t >> 6;                 // 0..1, k = ak0 + 2*i
    const int mg  = m0 + am;
    const int img = mg / HW;
    const int p   = mg - img*HW;
    const int py  = p / WW;
    const int px  = p - py*WW;
    const float* xb = x + (size_t)img * C1 * HW;

    // B load mapping: k fixed = t&15, o = t>>4 + 8*i
    const int bk  = t & 15;
    const int bo0 = t >> 4;

    const int tx = t & 15, ty = t >> 4;
    float acc[8][8];
    #pragma unroll
    for (int r = 0; r < 8; r++)
        #pragma unroll
        for (int c = 0; c < 8; c++) acc[r][c] = 0.f;

    for (int kb = 0; kb < KCONV; kb += 16) {
        #pragma unroll
        for (int i = 0; i < 8; i++) {
            int k  = ak0 + i*2;
            int kg = kb + k;
            int c  = kg / 9;
            int r9 = kg - c*9;
            int ky = r9 / 3;
            int kx = r9 - ky*3;
            int yy = py + ky - 1;
            int xx = px + kx - 1;
            float v = 0.f;
            if ((unsigned)yy < HH && (unsigned)xx < WW)
                v = __ldg(xb + c*HW + yy*WW + xx);
            As[k*68 + am] = v;
        }
        #pragma unroll
        for (int i = 0; i < 16; i++) {
            int o = bo0 + i*8;
            Bs[bk*132 + o] = __ldg(w + (size_t)o*KCONV + kb + bk);
        }
        __syncthreads();
        #pragma unroll
        for (int k = 0; k < 16; k++) {
            float4 a0 = *(const float4*)(As + k*68  + (ty<<2));
            float4 a1 = *(const float4*)(As + k*68  + (ty<<2) + 32);
            float4 b0 = *(const float4*)(Bs + k*132 + (tx<<2));
            float4 b1 = *(const float4*)(Bs + k*132 + (tx<<2) + 64);
            float ar[8] = {a0.x,a0.y,a0.z,a0.w,a1.x,a1.y,a1.z,a1.w};
            float br[8] = {b0.x,b0.y,b0.z,b0.w,b1.x,b1.y,b1.z,b1.w};
            #pragma unroll
            for (int r = 0; r < 8; r++)
                #pragma unroll
                for (int c = 0; c < 8; c++)
                    acc[r][c] = fmaf(ar[r], br[c], acc[r][c]);
        }
        __syncthreads();
    }

    // epilogue: h (NHWC) = silu(conv*scale + bias)
    #pragma unroll
    for (int c8 = 0; c8 < 8; c8++) {
        int n = (tx<<2) + (c8&3) + ((c8>>2)<<6);
        float inv = rsqrtf(bv[n] + EPSS);
        float sc  = bg[n]*inv;
        float bi  = bb[n] - bm[n]*sc;
        #pragma unroll
        for (int r8 = 0; r8 < 8; r8++) {
            int row = (ty<<2) + (r8&3) + ((r8>>2)<<5);
            float v = acc[r8][c8]*sc + bi;
            g_h[(size_t)(m0+row)*CM + n] = siluf(v);
        }
    }
}

// ---------------------------------------------------------------------------
// Kernel 2: depthwise 3x3 + bias -> LayerNorm over 128 channels -> exact GELU
// one block per pixel, one thread per channel
// ---------------------------------------------------------------------------
__global__ __launch_bounds__(128) void dw_ln_gelu(
    const float* __restrict__ wdw, const float* __restrict__ bdw,
    const float* __restrict__ lg,  const float* __restrict__ lb)
{
    const int pix = blockIdx.x;
    const int c   = threadIdx.x;
    const int img = pix / HW;
    const int p   = pix - img*HW;
    const int py  = p / WW;
    const int px  = p - py*WW;
    const float* hb = g_h + (size_t)img*HW*CM;

    float s = bdw[c];
    #pragma unroll
    for (int ky = 0; ky < 3; ky++) {
        int yy = py + ky - 1;
        if ((unsigned)yy >= HH) continue;
        #pragma unroll
        for (int kx = 0; kx < 3; kx++) {
            int xx = px + kx - 1;
            if ((unsigned)xx >= WW) continue;
            s = fmaf(hb[(size_t)(yy*WW + xx)*CM + c], wdw[c*9 + ky*3 + kx], s);
        }
    }
    // block reduction (128 threads = 4 warps) for mean / var
    float r1 = s, r2 = s*s;
    #pragma unroll
    for (int o = 16; o; o >>= 1) {
        r1 += __shfl_xor_sync(0xffffffffu, r1, o);
        r2 += __shfl_xor_sync(0xffffffffu, r2, o);
    }
    __shared__ float rb[8];
    int wi = c >> 5;
    if ((c & 31) == 0) { rb[wi] = r1; rb[4+wi] = r2; }
    __syncthreads();
    float sum = rb[0]+rb[1]+rb[2]+rb[3];
    float ssq = rb[4]+rb[5]+rb[6]+rb[7];
    float mu  = sum * (1.f/CM);
    float var = ssq * (1.f/CM) - mu*mu;
    float tn  = (s - mu) * rsqrtf(var + EPSS) * lg[c] + lb[c];
    float ge  = 0.5f * tn * (1.f + erff(tn * 0.70710678118654752f));
    g_t[(size_t)pix*CM + c] = ge;
}

// ---------------------------------------------------------------------------
// Kernel 3/4/6: generic GEMM, K=128, M tile 64, N tile 128, 8x8 microtile.
// B is [K x Nout] row-major, optionally split into two column blocks (B|B2).
// EPI 0: C = acc + bias           (value proj, NHWC)
// EPI 1: C = acc + bias(|bias2)   (offset+mask logits, Nout=108)
// EPI 2: out = resid + silu(bn(acc + eb))  written NCHW via smem transpose
// ---------------------------------------------------------------------------
template<int EPI>
__global__ __launch_bounds__(128) void gemm_k128(
    const float* __restrict__ A,
    const float* __restrict__ B, const float* __restrict__ B2,
    int N1, int Nout,
    const float* __restrict__ bias, const float* __restrict__ bias2,
    float* __restrict__ C,
    const float* __restrict__ eb,
    const float* __restrict__ bg, const float* __restrict__ bb,
    const float* __restrict__ bm, const float* __restrict__ bv,
    const float* __restrict__ resid)
{
    __shared__ __align__(16) float sm[(EPI == 2) ? 128*65 : (16*68 + 16*132)];
    float* As = sm;
    float* Bs = sm + 16*68;

    const int t  = threadIdx.x;
    const int m0 = blockIdx.x * 64;
    const int n0 = blockIdx.y * 128;

    const int ak  = t & 15;          // A: k fixed
    const int am0 = t >> 4;          // m = am0 + 8*i
    const int tx = t & 15, ty = t >> 4;

    float acc[8][8];
    #pragma unroll
    for (int r = 0; r < 8; r++)
        #pragma unroll
        for (int c = 0; c < 8; c++) acc[r][c] = 0.f;

    const int j = n0 + t;            // B: column fixed per thread
    for (int kb = 0; kb < 128; kb += 16) {
        #pragma unroll
        for (int i = 0; i < 8; i++) {
            int m = am0 + i*8;
            As[ak*68 + m] = A[(size_t)(m0+m)*128 + kb + ak];
        }
        #pragma unroll
        for (int i = 0; i < 16; i++) {
            float v = 0.f;
            if (j < N1)        v = B[(size_t)(kb+i)*N1 + j];
            else if (j < Nout) v = B2[(size_t)(kb+i)*(Nout-N1) + (j-N1)];
            Bs[i*132 + t] = v;
        }
        __syncthreads();
        #pragma unroll
        for (int k = 0; k < 16; k++) {
            float4 a0 = *(const float4*)(As + k*68  + (ty<<2));
            float4 a1 = *(const float4*)(As + k*68  + (ty<<2) + 32);
            float4 b0 = *(const float4*)(Bs + k*132 + (tx<<2));
            float4 b1 = *(const float4*)(Bs + k*132 + (tx<<2) + 64);
            float ar[8] = {a0.x,a0.y,a0.z,a0.w,a1.x,a1.y,a1.z,a1.w};
            float br[8] = {b0.x,b0.y,b0.z,b0.w,b1.x,b1.y,b1.z,b1.w};
            #pragma unroll
            for (int r = 0; r < 8; r++)
                #pragma unroll
                for (int c = 0; c < 8; c++)
                    acc[r][c] = fmaf(ar[r], br[c], acc[r][c]);
        }
        __syncthreads();
    }

    if (EPI != 2) {
        // per-column bias (split lookup)
        float bvs[8];
        #pragma unroll
        for (int c8 = 0; c8 < 8; c8++) {
            int jj = n0 + (tx<<2) + (c8&3) + ((c8>>2)<<6);
            float b = 0.f;
            if (jj < N1)        b = bias[jj];
            else if (jj < Nout) b = bias2[jj - N1];
            bvs[c8] = b;
        }
        #pragma unroll
        for (int r8 = 0; r8 < 8; r8++) {
            int row = (ty<<2) + (r8&3) + ((r8>>2)<<5);
            size_t base = (size_t)(m0+row)*Nout + n0;
            #pragma unroll
            for (int cH = 0; cH < 2; cH++) {
                int n = (tx<<2) + (cH<<6);
                if (n0 + n < Nout) {
                    float4 o;
                    o.x = acc[r8][cH*4+0] + bvs[cH*4+0];
                    o.y = acc[r8][cH*4+1] + bvs[cH*4+1];
                    o.z = acc[r8][cH*4+2] + bvs[cH*4+2];
                    o.w = acc[r8][cH*4+3] + bvs[cH*4+3];
                    *(float4*)(C + base + n) = o;
                }
            }
        }
    } else {
        // stage silu(bn(acc+bias)) transposed in smem, then coalesced NCHW write
        #pragma unroll
        for (int c8 = 0; c8 < 8; c8++) {
            int n  = (tx<<2) + (c8&3) + ((c8>>2)<<6);
            int co = n0 + n;
            float inv = rsqrtf(bv[co] + EPSS);
            float sc  = bg[co]*inv;
            float bi  = bb[co] - bm[co]*sc;
            float bo  = eb[co];
            #pragma unroll
            for (int r8 = 0; r8 < 8; r8++) {
                int row = (ty<<2) + (r8&3) + ((r8>>2)<<5);
                float v = (acc[r8][c8] + bo)*sc + bi;
                sm[n*65 + row] = siluf(v);
            }
        }
        __syncthreads();
        const int mloc = t & 63;
        const int nb0  = t >> 6;     // 0/1
        const int mg   = m0 + mloc;
        const int img  = mg / HW;
        const int pp   = mg - img*HW;
        const size_t obase = (size_t)img*C2*HW + pp;
        #pragma unroll
        for (int i = 0; i < 64; i++) {
            int n = nb0 + i*2;
            size_t adr = obase + (size_t)(n0 + n)*HW;
            C[adr] = resid[adr] + sm[n*65 + mloc];
        }
    }
}

// ---------------------------------------------------------------------------
// Kernel 5: DCNv3 core. One warp per (pixel, group); lane = channel in group.
// Softmax of the 9 mask logits computed in-register (lane-redundant).
// Padded-coordinate algebra: px = ix + (k/3) + dx ; py = iy + (k%3) + dy,
// padded value nonzero iff 1 <= coord <= 56  ->  value[coord-1].
// ---------------------------------------------------------------------------
__global__ __launch_bounds__(256) void dcn_core()
{
    int gw   = (blockIdx.x*blockDim.x + threadIdx.x) >> 5;
    int lane = threadIdx.x & 31;
    if (gw >= NPIX*GG) return;
    int pid = gw >> 2;
    int g   = gw & 3;
    int img = pid / HW;
    int p   = pid - img*HW;
    int iy  = p / WW;
    int ix  = p - iy*WW;

    const float* om = g_om + (size_t)pid*NOM;
    float m9[9]; float mx = -1e30f;
    #pragma unroll
    for (int k = 0; k < 9; k++) { m9[k] = om[72 + g*9 + k]; mx = fmaxf(mx, m9[k]); }
    float se = 0.f;
    #pragma unroll
    for (int k = 0; k < 9; k++) { m9[k] = expf(m9[k] - mx); se += m9[k]; }
    float inv = 1.f / se;

    const float* vb = g_v + (size_t)img*HW*CM + g*GC + lane;
    float acc = 0.f;
    #pragma unroll
    for (int k = 0; k < 9; k++) {
        float dx = om[(g*9 + k)*2];
        float dy = om[(g*9 + k)*2 + 1];
        int kxi = k / 3;
        int kyi = k - kxi*3;
        float fx = (float)(ix + kxi) + dx;   // padded x coord
        float fy = (float)(iy + kyi) + dy;   // padded y coord
        float x0f = floorf(fx), y0f = floorf(fy);
        float wx = fx - x0f, wy = fy - y0f;
        int x0 = (int)x0f, y0 = (int)y0f;
        int xm = x0 - 1, ym = y0 - 1;        // unpadded value coords
        float v00 = 0.f, v01 = 0.f, v10 = 0.f, v11 = 0.f;
        bool vx0 = (unsigned)xm     < WW;
        bool vx1 = (unsigned)(xm+1) < WW;
        bool vy0 = (unsigned)ym     < HH;
        bool vy1 = (unsigned)(ym+1) < HH;
        if (vy0 && vx0) v00 = vb[(size_t)(ym*WW + xm      )*CM];
        if (vy0 && vx1) v01 = vb[(size_t)(ym*WW + xm + 1  )*CM];
        if (vy1 && vx0) v10 = vb[(size_t)((ym+1)*WW + xm  )*CM];
        if (vy1 && vx1) v11 = vb[(size_t)((ym+1)*WW + xm+1)*CM];
        float sv = v00*(1.f-wy)*(1.f-wx) + v01*(1.f-wy)*wx
                 + v10*wy*(1.f-wx)       + v11*wy*wx;
        acc = fmaf(m9[k]*inv, sv, acc);
    }
    g_o[(size_t)pid*CM + g*GC + lane] = acc;
}

// ---------------------------------------------------------------------------
extern "C" void kernel_launch(void* const* d_in, const int* in_sizes, int n_in,
                              void* d_out, int out_size)
{
    const float* x    = (const float*)d_in[0];
    const float* wcv1 = (const float*)d_in[1];
    const float* bn1g = (const float*)d_in[2];
    const float* bn1b = (const float*)d_in[3];
    const float* bn1m = (const float*)d_in[4];
    const float* bn1v = (const float*)d_in[5];
    const float* wdw  = (const float*)d_in[6];
    const float* bdw  = (const float*)d_in[7];
    const float* lng  = (const float*)d_in[8];
    const float* lnb  = (const float*)d_in[9];
    const float* winp = (const float*)d_in[10];
    const float* binp = (const float*)d_in[11];
    const float* woff = (const float*)d_in[12];
    const float* boff = (const float*)d_in[13];
    const float* wmsk = (const float*)d_in[14];
    const float* bmsk = (const float*)d_in[15];
    const float* wout = (const float*)d_in[16];
    const float* bout = (const float*)d_in[17];
    const float* bn2g = (const float*)d_in[18];
    const float* bn2b = (const float*)d_in[19];
    const float* bn2m = (const float*)d_in[20];
    const float* bn2v = (const float*)d_in[21];
    float* out = (float*)d_out;

    float *ph, *pt, *pv, *pom, *po;
    cudaGetSymbolAddress((void**)&ph,  g_h);
    cudaGetSymbolAddress((void**)&pt,  g_t);
    cudaGetSymbolAddress((void**)&pv,  g_v);
    cudaGetSymbolAddress((void**)&pom, g_om);
    cudaGetSymbolAddress((void**)&po,  g_o);

    // 1) conv1 + BN + SiLU -> g_h (NHWC)
    conv1_bn_silu<<<NPIX/64, 128>>>(x, wcv1, bn1g, bn1b, bn1m, bn1v);
    // 2) depthwise + LN + GELU -> g_t (NHWC)
    dw_ln_gelu<<<NPIX, 128>>>(wdw, bdw, lng, lnb);
    // 3) value projection -> g_v
    gemm_k128<0><<<dim3(NPIX/64, 1), 128>>>(ph, winp, nullptr, CM, CM,
        binp, nullptr, pv, nullptr, nullptr, nullptr, nullptr, nullptr, nullptr);
    // 4) offsets + mask logits -> g_om (Nout=108)
    gemm_k128<1><<<dim3(NPIX/64, 1), 128>>>(pt, woff, wmsk, 72, NOM,
        boff, bmsk, pom, nullptr, nullptr, nullptr, nullptr, nullptr, nullptr);
    // 5) deformable sampling -> g_o
    dcn_core<<<(NPIX*GG)/8, 256>>>();
    // 6) output projection + BN + SiLU + residual -> out (NCHW)
    gemm_k128<2><<<dim3(NPIX/64, 2), 128>>>(po, wout, nullptr, C2, C2,
        nullptr, nullptr, out, bout, bn2g, bn2b, bn2m, bn2v, x);
}

// round 4
// speedup vs baseline: 1.2749x; 1.2749x over previous
#include <cuda_runtime.h>
#include <cuda_bf16.h>
#include <math.h>
#include <stdint.h>

#define NB   8
#define C1   256
#define C2   256
#define CM   128
#define HH   56
#define WW   56
#define HW   3136
#define NPIX (NB*HW)
#define GG   4
#define GC   32
#define EPSS 1e-5f
#define NOM  108
#define NCHUNK 36
#define NSTG 3
#define XPW  66
#define STGB 65536

// scratch (device globals: allocation-free rule)
__device__ float g_h [NPIX*CM];
__device__ float g_t [NPIX*CM];
__device__ float g_v [NPIX*CM];
__device__ float g_om[NPIX*NOM];
__device__ float g_o [NPIX*CM];
__device__ __nv_bfloat16 g_xp_hi[8*58*XPW*256];
__device__ __nv_bfloat16 g_xp_lo[8*58*XPW*256];
__device__ __nv_bfloat16 g_wb_hi[NCHUNK*128*64];
__device__ __nv_bfloat16 g_wb_lo[NCHUNK*128*64];

__device__ __forceinline__ float siluf(float v){ return v / (1.f + expf(-v)); }

__device__ __forceinline__ uint32_t smem_to_u32(const void* p) {
    uint32_t a;
    asm("{ .reg .u64 t; cvta.to.shared.u64 t, %1; cvt.u32.u64 %0, t; }" : "=r"(a) : "l"(p));
    return a;
}
#define SWZ128(o) ((o) ^ (((o) >> 3) & 0x70))
#define CP_ASYNC16(sa, gp) \
    asm volatile("cp.async.cg.shared.global [%0], [%1], 16;" \
        :: "r"((uint32_t)(sa)), "l"(gp) : "memory")

__device__ __forceinline__ void ldsm4(uint32_t* r, uint32_t addr) {
    asm volatile("ldmatrix.sync.aligned.m8n8.x4.shared.b16 {%0,%1,%2,%3}, [%4];"
        : "=r"(r[0]), "=r"(r[1]), "=r"(r[2]), "=r"(r[3]) : "r"(addr));
}
__device__ __forceinline__ void mma16816(float* d, const uint32_t* a, uint32_t b0, uint32_t b1) {
    asm volatile("mma.sync.aligned.m16n8k16.row.col.f32.bf16.bf16.f32 "
        "{%0,%1,%2,%3}, {%4,%5,%6,%7}, {%8,%9}, {%0,%1,%2,%3};"
        : "+f"(d[0]), "+f"(d[1]), "+f"(d[2]), "+f"(d[3])
        : "r"(a[0]), "r"(a[1]), "r"(a[2]), "r"(a[3]), "r"(b0), "r"(b1));
}

// ===================== prep: pad/transpose/split x =====================
__global__ __launch_bounds__(256) void xprep(const float* __restrict__ x)
{
    const int b = blockIdx.x, img = b / 58, yp = b % 58;
    const size_t rowbase = ((size_t)img*58 + yp) * (XPW*256);
    const int t = threadIdx.x;
    uint2 z2 = make_uint2(0u, 0u);
    for (int i = t; i < XPW*256/4; i += 256) {
        ((uint2*)(g_xp_hi + rowbase))[i] = z2;
        ((uint2*)(g_xp_lo + rowbase))[i] = z2;
    }
    if (yp == 0 || yp == 57) return;
    __syncthreads();
    const int oy = yp - 1;
    __shared__ float sm[128*57];
    for (int pass = 0; pass < 2; pass++) {
        for (int i = t; i < 128*56; i += 256) {
            int c = i / 56, ox = i % 56;
            sm[c*57 + ox] = x[((size_t)(img*256 + pass*128 + c))*HW + oy*WW + ox];
        }
        __syncthreads();
        for (int i = t; i < 56*128; i += 256) {
            int ox = i >> 7, c = i & 127;
            float v = sm[c*57 + ox];
            __nv_bfloat16 h = __float2bfloat16(v);
            size_t a = rowbase + (size_t)(ox+1)*256 + pass*128 + c;
            g_xp_hi[a] = h;
            g_xp_lo[a] = __float2bfloat16(v - __bfloat162float(h));
        }
        __syncthreads();
    }
}

// weights: w[o][c*9+tap] -> [chunk=tap*4+cc][o][ci]
__global__ __launch_bounds__(256) void wprep(const float* __restrict__ w)
{
    int idx = blockIdx.x*256 + threadIdx.x;
    if (idx >= NCHUNK*128*64) return;
    int ci = idx & 63, o = (idx >> 6) & 127, ch = idx >> 13;
    int tap = ch >> 2, cc = ch & 3;
    float v = w[(size_t)o*2304 + (cc*64 + ci)*9 + tap];
    __nv_bfloat16 h = __float2bfloat16(v);
    g_wb_hi[idx] = h;
    g_wb_lo[idx] = __float2bfloat16(v - __bfloat162float(h));
}

// ===================== conv1 via mma.sync bf16 hi/lo =====================
// CTA = (img, 2 output rows): M=128 (2y x 64x), N=128 out ch, K=36x64.
// 8 warps: 4 m x 2 n, warp tile 32x64. 3-stage cp.async pipeline.
__global__ __launch_bounds__(256) void conv1_mma(
    const float* __restrict__ bg, const float* __restrict__ bb,
    const float* __restrict__ bm, const float* __restrict__ bv)
{
    extern __shared__ char smraw[];
    char* smA = smraw + ((1024 - (smem_to_u32(smraw) & 1023)) & 1023);
    const uint32_t sb = smem_to_u32(smA);
    __shared__ float s_sc[128], s_sh[128];

    const int t = threadIdx.x, wid = t >> 5, lane = t & 31;
    const int img = blockIdx.x / 28, oy0 = (blockIdx.x % 28) * 2;

    if (t < 128) {
        float inv = rsqrtf(bv[t] + EPSS);
        float sc = bg[t]*inv;
        s_sc[t] = sc; s_sh[t] = bb[t] - bm[t]*sc;
    }

    // loader mapping: 256 threads x 16 cp.async = 4096 x 16B per stage
    const int col16 = t & 7;     // 16B column within 128B row
    const int r0    = t >> 3;    // rows r0 + 32*jj
    auto issue = [&](int j, int d) {
        int tap = j >> 2, cc = j & 3;
        int ky = tap / 3, kx = tap - ky*3;
        uint32_t st = sb + d*STGB;
        size_t xoff = (((size_t)(img*58 + oy0 + ky))*XPW + kx)*256 + cc*64 + col16*8;
        const __nv_bfloat16* axh = g_xp_hi + xoff;
        const __nv_bfloat16* axl = g_xp_lo + xoff;
        const __nv_bfloat16* bwh = g_wb_hi + (size_t)j*8192 + col16*8;
        const __nv_bfloat16* bwl = g_wb_lo + (size_t)j*8192 + col16*8;
        #pragma unroll
        for (int jj = 0; jj < 4; jj++) {
            int m = r0 + 32*jj;
            uint32_t so = SWZ128((uint32_t)(m*128 + col16*16));
            size_t ga = ((size_t)(m >> 6))*(XPW*256) + (size_t)(m & 63)*256;
            CP_ASYNC16(st +         so, axh + ga);
            CP_ASYNC16(st + 16384 + so, axl + ga);
            CP_ASYNC16(st + 32768 + so, bwh + (size_t)m*64);
            CP_ASYNC16(st + 49152 + so, bwl + (size_t)m*64);
        }
        asm volatile("cp.async.commit_group;" ::: "memory");
    };

    const int wm = wid & 3, wn = wid >> 2;
    float acc[2][8][4];
    #pragma unroll
    for (int a = 0; a < 2; a++)
        #pragma unroll
        for (int b = 0; b < 8; b++)
            #pragma unroll
            for (int c = 0; c < 4; c++) acc[a][b][c] = 0.f;

    // ldmatrix lane -> (row, colbyte) mapping (same for A x4 and B x4)
    const int lg = lane >> 3, lri = lane & 7;
    const int rsel = (lg & 1)*8 + lri;
    const int csel = (lg >> 1)*16;

    issue(0, 0); issue(1, 1);
    for (int i = 0; i < NCHUNK; i++) {
        if (i < NCHUNK-1) asm volatile("cp.async.wait_group 1;" ::: "memory");
        else              asm volatile("cp.async.wait_group 0;" ::: "memory");
        __syncthreads();
        if (i + 2 < NCHUNK) issue(i + 2, (i + 2) % NSTG);

        uint32_t base = sb + (i % NSTG)*STGB;
        #pragma unroll
        for (int ks = 0; ks < 4; ks++) {
            int cb = ks*32 + csel;
            uint32_t ah[2][4], al[2][4], bbf[4][4];
            #pragma unroll
            for (int mf = 0; mf < 2; mf++) {
                int row = wm*32 + mf*16 + rsel;
                ldsm4(ah[mf], base + SWZ128((uint32_t)(row*128 + cb)));
            }
            #pragma unroll
            for (int nb = 0; nb < 4; nb++) {
                int row = wn*64 + nb*16 + rsel;
                ldsm4(bbf[nb], base + 32768 + SWZ128((uint32_t)(row*128 + cb)));
            }
            #pragma unroll
            for (int mf = 0; mf < 2; mf++)
                #pragma unroll
                for (int nf = 0; nf < 8; nf++)
                    mma16816(acc[mf][nf], ah[mf], bbf[nf>>1][nf&1], bbf[nf>>1][(nf&1)+2]);
            // Al x Bh
            #pragma unroll
            for (int mf = 0; mf < 2; mf++) {
                int row = wm*32 + mf*16 + rsel;
                ldsm4(al[mf], base + 16384 + SWZ128((uint32_t)(row*128 + cb)));
            }
            #pragma unroll
            for (int mf = 0; mf < 2; mf++)
                #pragma unroll
                for (int nf = 0; nf < 8; nf++)
                    mma16816(acc[mf][nf], al[mf], bbf[nf>>1][nf&1], bbf[nf>>1][(nf&1)+2]);
            // Ah x Bl (reload B regs from lo buffer)
            #pragma unroll
            for (int nb = 0; nb < 4; nb++) {
                int row = wn*64 + nb*16 + rsel;
                ldsm4(bbf[nb], base + 49152 + SWZ128((uint32_t)(row*128 + cb)));
            }
            #pragma unroll
            for (int mf = 0; mf < 2; mf++)
                #pragma unroll
                for (int nf = 0; nf < 8; nf++)
                    mma16816(acc[mf][nf], ah[mf], bbf[nf>>1][nf&1], bbf[nf>>1][(nf&1)+2]);
        }
    }

    // epilogue: BN + SiLU, float2 NHWC stores
    const int ro = lane >> 2, co = (lane & 3) << 1;
    #pragma unroll
    for (int mf = 0; mf < 2; mf++) {
        #pragma unroll
        for (int half = 0; half < 2; half++) {
            int m = wm*32 + mf*16 + half*8 + ro;
            int ox = m & 63, ysub = m >> 6;
            if (ox < 56) {
                float* dst = g_h + ((size_t)(img*HW + (oy0 + ysub)*WW + ox))*CM;
                #pragma unroll
                for (int nf = 0; nf < 8; nf++) {
                    int c = wn*64 + nf*8 + co;
                    float2 o2;
                    o2.x = siluf(acc[mf][nf][half*2+0]*s_sc[c]   + s_sh[c]);
                    o2.y = siluf(acc[mf][nf][half*2+1]*s_sc[c+1] + s_sh[c+1]);
                    *(float2*)(dst + c) = o2;
                }
            }
        }
    }
}

// ===================== round-1 kernels (unchanged) =====================
__global__ __launch_bounds__(128) void dw_ln_gelu(
    const float* __restrict__ wdw, const float* __restrict__ bdw,
    const float* __restrict__ lg,  const float* __restrict__ lb)
{
    const int pix = blockIdx.x;
    const int c   = threadIdx.x;
    const int img = pix / HW;
    const int p   = pix - img*HW;
    const int py  = p / WW;
    const int px  = p - py*WW;
    const float* hb = g_h + (size_t)img*HW*CM;

    float s = bdw[c];
    #pragma unroll
    for (int ky = 0; ky < 3; ky++) {
        int yy = py + ky - 1;
        if ((unsigned)yy >= HH) continue;
        #pragma unroll
        for (int kx = 0; kx < 3; kx++) {
            int xx = px + kx - 1;
            if ((unsigned)xx >= WW) continue;
            s = fmaf(hb[(size_t)(yy*WW + xx)*CM + c], wdw[c*9 + ky*3 + kx], s);
        }
    }
    float r1 = s, r2 = s*s;
    #pragma unroll
    for (int o = 16; o; o >>= 1) {
        r1 += __shfl_xor_sync(0xffffffffu, r1, o);
        r2 += __shfl_xor_sync(0xffffffffu, r2, o);
    }
    __shared__ float rb[8];
    int wi = c >> 5;
    if ((c & 31) == 0) { rb[wi] = r1; rb[4+wi] = r2; }
    __syncthreads();
    float sum = rb[0]+rb[1]+rb[2]+rb[3];
    float ssq = rb[4]+rb[5]+rb[6]+rb[7];
    float mu  = sum * (1.f/CM);
    float var = ssq * (1.f/CM) - mu*mu;
    float tn  = (s - mu) * rsqrtf(var + EPSS) * lg[c] + lb[c];
    g_t[(size_t)pix*CM + c] = 0.5f * tn * (1.f + erff(tn * 0.70710678118654752f));
}

template<int EPI>
__global__ __launch_bounds__(128) void gemm_k128(
    const float* __restrict__ A,
    const float* __restrict__ B, const float* __restrict__ B2,
    int N1, int Nout,
    const float* __restrict__ bias, const float* __restrict__ bias2,
    float* __restrict__ C,
    const float* __restrict__ eb,
    const float* __restrict__ bg, const float* __restrict__ bb,
    const float* __restrict__ bm, const float* __restrict__ bv,
    const float* __restrict__ resid)
{
    __shared__ __align__(16) float sm[(EPI == 2) ? 128*65 : (16*68 + 16*132)];
    float* As = sm;
    float* Bs = sm + 16*68;
    const int t  = threadIdx.x;
    const int m0 = blockIdx.x * 64;
    const int n0 = blockIdx.y * 128;
    const int ak  = t & 15;
    const int am0 = t >> 4;
    const int tx = t & 15, ty = t >> 4;

    float acc[8][8];
    #pragma unroll
    for (int r = 0; r < 8; r++)
        #pragma unroll
        for (int c = 0; c < 8; c++) acc[r][c] = 0.f;

    const int j = n0 + t;
    for (int kb = 0; kb < 128; kb += 16) {
        #pragma unroll
        for (int i = 0; i < 8; i++) {
            int m = am0 + i*8;
            As[ak*68 + m] = A[(size_t)(m0+m)*128 + kb + ak];
        }
        #pragma unroll
        for (int i = 0; i < 16; i++) {
            float v = 0.f;
            if (j < N1)        v = B[(size_t)(kb+i)*N1 + j];
            else if (j < Nout) v = B2[(size_t)(kb+i)*(Nout-N1) + (j-N1)];
            Bs[i*132 + t] = v;
        }
        __syncthreads();
        #pragma unroll
        for (int k = 0; k < 16; k++) {
            float4 a0 = *(const float4*)(As + k*68  + (ty<<2));
            float4 a1 = *(const float4*)(As + k*68  + (ty<<2) + 32);
            float4 b0 = *(const float4*)(Bs + k*132 + (tx<<2));
            float4 b1 = *(const float4*)(Bs + k*132 + (tx<<2) + 64);
            float ar[8] = {a0.x,a0.y,a0.z,a0.w,a1.x,a1.y,a1.z,a1.w};
            float br[8] = {b0.x,b0.y,b0.z,b0.w,b1.x,b1.y,b1.z,b1.w};
            #pragma unroll
            for (int r = 0; r < 8; r++)
                #pragma unroll
                for (int c = 0; c < 8; c++)
                    acc[r][c] = fmaf(ar[r], br[c], acc[r][c]);
        }
        __syncthreads();
    }

    if (EPI != 2) {
        float bvs[8];
        #pragma unroll
        for (int c8 = 0; c8 < 8; c8++) {
            int jj = n0 + (tx<<2) + (c8&3) + ((c8>>2)<<6);
            float b = 0.f;
            if (jj < N1)        b = bias[jj];
            else if (jj < Nout) b = bias2[jj - N1];
            bvs[c8] = b;
        }
        #pragma unroll
        for (int r8 = 0; r8 < 8; r8++) {
            int row = (ty<<2) + (r8&3) + ((r8>>2)<<5);
            size_t base = (size_t)(m0+row)*Nout + n0;
            #pragma unroll
            for (int cH = 0; cH < 2; cH++) {
                int n = (tx<<2) + (cH<<6);
                if (n0 + n < Nout) {
                    float4 o;
                    o.x = acc[r8][cH*4+0] + bvs[cH*4+0];
                    o.y = acc[r8][cH*4+1] + bvs[cH*4+1];
                    o.z = acc[r8][cH*4+2] + bvs[cH*4+2];
                    o.w = acc[r8][cH*4+3] + bvs[cH*4+3];
                    *(float4*)(C + base + n) = o;
                }
            }
        }
    } else {
        #pragma unroll
        for (int c8 = 0; c8 < 8; c8++) {
            int n  = (tx<<2) + (c8&3) + ((c8>>2)<<6);
            int co = n0 + n;
            float inv = rsqrtf(bv[co] + EPSS);
            float sc  = bg[co]*inv;
            float bi  = bb[co] - bm[co]*sc;
            float bo  = eb[co];
            #pragma unroll
            for (int r8 = 0; r8 < 8; r8++) {
                int row = (ty<<2) + (r8&3) + ((r8>>2)<<5);
                float v = (acc[r8][c8] + bo)*sc + bi;
                sm[n*65 + row] = siluf(v);
            }
        }
        __syncthreads();
        const int mloc = t & 63;
        const int nb0  = t >> 6;
        const int mg   = m0 + mloc;
        const int img  = mg / HW;
        const int pp   = mg - img*HW;
        const size_t obase = (size_t)img*C2*HW + pp;
        #pragma unroll
        for (int i = 0; i < 64; i++) {
            int n = nb0 + i*2;
            size_t adr = obase + (size_t)(n0 + n)*HW;
            C[adr] = resid[adr] + sm[n*65 + mloc];
        }
    }
}

__global__ __launch_bounds__(256) void dcn_core()
{
    int gw   = (blockIdx.x*blockDim.x + threadIdx.x) >> 5;
    int lane = threadIdx.x & 31;
    if (gw >= NPIX*GG) return;
    int pid = gw >> 2;
    int g   = gw & 3;
    int img = pid / HW;
    int p   = pid - img*HW;
    int iy  = p / WW;
    int ix  = p - iy*WW;

    const float* om = g_om + (size_t)pid*NOM;
    float m9[9]; float mx = -1e30f;
    #pragma unroll
    for (int k = 0; k < 9; k++) { m9[k] = om[72 + g*9 + k]; mx = fmaxf(mx, m9[k]); }
    float se = 0.f;
    #pragma unroll
    for (int k = 0; k < 9; k++) { m9[k] = expf(m9[k] - mx); se += m9[k]; }
    float inv = 1.f / se;

    const float* vb = g_v + (size_t)img*HW*CM + g*GC + lane;
    float acc = 0.f;
    #pragma unroll
    for (int k = 0; k < 9; k++) {
        float dx = om[(g*9 + k)*2];
        float dy = om[(g*9 + k)*2 + 1];
        int kxi = k / 3;
        int kyi = k - kxi*3;
        float fx = (float)(ix + kxi) + dx;
        float fy = (float)(iy + kyi) + dy;
        float x0f = floorf(fx), y0f = floorf(fy);
        float wx = fx - x0f, wy = fy - y0f;
        int xm = (int)x0f - 1, ym = (int)y0f - 1;
        float v00 = 0.f, v01 = 0.f, v10 = 0.f, v11 = 0.f;
        bool vx0 = (unsigned)xm     < WW;
        bool vx1 = (unsigned)(xm+1) < WW;
        bool vy0 = (unsigned)ym     < HH;
        bool vy1 = (unsigned)(ym+1) < HH;
        if (vy0 && vx0) v00 = vb[(size_t)(ym*WW + xm      )*CM];
        if (vy0 && vx1) v01 = vb[(size_t)(ym*WW + xm + 1  )*CM];
        if (vy1 && vx0) v10 = vb[(size_t)((ym+1)*WW + xm  )*CM];
        if (vy1 && vx1) v11 = vb[(size_t)((ym+1)*WW + xm+1)*CM];
        float sv = v00*(1.f-wy)*(1.f-wx) + v01*(1.f-wy)*wx
                 + v10*wy*(1.f-wx)       + v11*wy*wx;
        acc = fmaf(m9[k]*inv, sv, acc);
    }
    g_o[(size_t)pid*CM + g*GC + lane] = acc;
}

// ===================== launch =====================
extern "C" void kernel_launch(void* const* d_in, const int* in_sizes, int n_in,
                              void* d_out, int out_size)
{
    const float* x    = (const float*)d_in[0];
    const float* wcv1 = (const float*)d_in[1];
    const float* bn1g = (const float*)d_in[2];
    const float* bn1b = (const float*)d_in[3];
    const float* bn1m = (const float*)d_in[4];
    const float* bn1v = (const float*)d_in[5];
    const float* wdw  = (const float*)d_in[6];
    const float* bdw  = (const float*)d_in[7];
    const float* lng  = (const float*)d_in[8];
    const float* lnb  = (const float*)d_in[9];
    const float* winp = (const float*)d_in[10];
    const float* binp = (const float*)d_in[11];
    const float* woff = (const float*)d_in[12];
    const float* boff = (const float*)d_in[13];
    const float* wmsk = (const float*)d_in[14];
    const float* bmsk = (const float*)d_in[15];
    const float* wout = (const float*)d_in[16];
    const float* bout = (const float*)d_in[17];
    const float* bn2g = (const float*)d_in[18];
    const float* bn2b = (const float*)d_in[19];
    const float* bn2m = (const float*)d_in[20];
    const float* bn2v = (const float*)d_in[21];
    float* out = (float*)d_out;

    float *ph, *pt, *pv, *pom, *po;
    cudaGetSymbolAddress((void**)&ph,  g_h);
    cudaGetSymbolAddress((void**)&pt,  g_t);
    cudaGetSymbolAddress((void**)&pv,  g_v);
    cudaGetSymbolAddress((void**)&pom, g_om);
    cudaGetSymbolAddress((void**)&po,  g_o);

    const int smem_conv = NSTG*STGB + 1024;
    cudaFuncSetAttribute(conv1_mma, cudaFuncAttributeMaxDynamicSharedMemorySize, smem_conv);

    xprep<<<8*58, 256>>>(x);
    wprep<<<(NCHUNK*128*64 + 255)/256, 256>>>(wcv1);
    conv1_mma<<<8*28, 256, smem_conv>>>(bn1g, bn1b, bn1m, bn1v);
    dw_ln_gelu<<<NPIX, 128>>>(wdw, bdw, lng, lnb);
    gemm_k128<0><<<dim3(NPIX/64, 1), 128>>>(ph, winp, nullptr, CM, CM,
        binp, nullptr, pv, nullptr, nullptr, nullptr, nullptr, nullptr, nullptr);
    gemm_k128<1><<<dim3(NPIX/64, 1), 128>>>(pt, woff, wmsk, 72, NOM,
        boff, bmsk, pom, nullptr, nullptr, nullptr, nullptr, nullptr, nullptr);
    dcn_core<<<(NPIX*GG)/8, 256>>>();
    gemm_k128<2><<<dim3(NPIX/64, 2), 128>>>(po, wout, nullptr, C2, C2,
        nullptr, nullptr, out, bout, bn2g, bn2b, bn2m, bn2v, x);
}

// round 5
// speedup vs baseline: 1.9614x; 1.5385x over previous
#include <cuda_runtime.h>
#include <cuda_bf16.h>
#include <math.h>
#include <stdint.h>

#define NB   8
#define C1   256
#define C2   256
#define CM   128
#define HH   56
#define WW   56
#define HW   3136
#define NPIX (NB*HW)
#define GG   4
#define GC   32
#define EPSS 1e-5f
#define NOM  108
#define NCHUNK 36
#define NSTG 3
#define XPW  66
#define STGB 65536

// scratch (device globals: allocation-free rule)
__device__ float g_h [NPIX*CM];
__device__ float g_v [NPIX*CM];
__device__ float g_om[NPIX*NOM];
__device__ __nv_bfloat16 g_xp_hi[8*58*XPW*256];
__device__ __nv_bfloat16 g_xp_lo[8*58*XPW*256];
__device__ __nv_bfloat16 g_wb_hi[NCHUNK*128*64];
__device__ __nv_bfloat16 g_wb_lo[NCHUNK*128*64];
// bf16 hi/lo A-operands for the K=128 GEMMs
__device__ __nv_bfloat16 g_hb_hi[NPIX*CM], g_hb_lo[NPIX*CM];
__device__ __nv_bfloat16 g_tb_hi[NPIX*CM], g_tb_lo[NPIX*CM];
__device__ __nv_bfloat16 g_ob_hi[NPIX*CM], g_ob_lo[NPIX*CM];
// B operands, layout [kc(2)][n][64 k], k-major rows
__device__ __nv_bfloat16 g_wv_hi [2*128*64], g_wv_lo [2*128*64];
__device__ __nv_bfloat16 g_wom_hi[2*128*64], g_wom_lo[2*128*64];
__device__ __nv_bfloat16 g_wo_hi [2*256*64], g_wo_lo [2*256*64];

__device__ __forceinline__ float siluf(float v){ return v / (1.f + expf(-v)); }

__device__ __forceinline__ uint32_t smem_to_u32(const void* p) {
    uint32_t a;
    asm("{ .reg .u64 t; cvta.to.shared.u64 t, %1; cvt.u32.u64 %0, t; }" : "=r"(a) : "l"(p));
    return a;
}
#define SWZ128(o) ((o) ^ (((o) >> 3) & 0x70))
#define CP_ASYNC16(sa, gp) \
    asm volatile("cp.async.cg.shared.global [%0], [%1], 16;" \
        :: "r"((uint32_t)(sa)), "l"(gp) : "memory")

__device__ __forceinline__ void ldsm4(uint32_t* r, uint32_t addr) {
    asm volatile("ldmatrix.sync.aligned.m8n8.x4.shared.b16 {%0,%1,%2,%3}, [%4];"
        : "=r"(r[0]), "=r"(r[1]), "=r"(r[2]), "=r"(r[3]) : "r"(addr));
}
__device__ __forceinline__ void mma16816(float* d, const uint32_t* a, uint32_t b0, uint32_t b1) {
    asm volatile("mma.sync.aligned.m16n8k16.row.col.f32.bf16.bf16.f32 "
        "{%0,%1,%2,%3}, {%4,%5,%6,%7}, {%8,%9}, {%0,%1,%2,%3};"
        : "+f"(d[0]), "+f"(d[1]), "+f"(d[2]), "+f"(d[3])
        : "r"(a[0]), "r"(a[1]), "r"(a[2]), "r"(a[3]), "r"(b0), "r"(b1));
}

// ===================== prep: pad/transpose/split x =====================
__global__ __launch_bounds__(256) void xprep(const float* __restrict__ x)
{
    const int b = blockIdx.x, img = b / 58, yp = b % 58;
    const size_t rowbase = ((size_t)img*58 + yp) * (XPW*256);
    const int t = threadIdx.x;
    uint2 z2 = make_uint2(0u, 0u);
    for (int i = t; i < XPW*256/4; i += 256) {
        ((uint2*)(g_xp_hi + rowbase))[i] = z2;
        ((uint2*)(g_xp_lo + rowbase))[i] = z2;
    }
    if (yp == 0 || yp == 57) return;
    __syncthreads();
    const int oy = yp - 1;
    __shared__ float sm[128*57];
    for (int pass = 0; pass < 2; pass++) {
        for (int i = t; i < 128*56; i += 256) {
            int c = i / 56, ox = i % 56;
            sm[c*57 + ox] = x[((size_t)(img*256 + pass*128 + c))*HW + oy*WW + ox];
        }
        __syncthreads();
        for (int i = t; i < 56*128; i += 256) {
            int ox = i >> 7, c = i & 127;
            float v = sm[c*57 + ox];
            __nv_bfloat16 h = __float2bfloat16(v);
            size_t a = rowbase + (size_t)(ox+1)*256 + pass*128 + c;
            g_xp_hi[a] = h;
            g_xp_lo[a] = __float2bfloat16(v - __bfloat162float(h));
        }
        __syncthreads();
    }
}

// conv weights: w[o][c*9+tap] -> [chunk=tap*4+cc][o][ci]
__global__ __launch_bounds__(256) void wprep(const float* __restrict__ w)
{
    int idx = blockIdx.x*256 + threadIdx.x;
    if (idx >= NCHUNK*128*64) return;
    int ci = idx & 63, o = (idx >> 6) & 127, ch = idx >> 13;
    int tap = ch >> 2, cc = ch & 3;
    float v = w[(size_t)o*2304 + (cc*64 + ci)*9 + tap];
    __nv_bfloat16 h = __float2bfloat16(v);
    g_wb_hi[idx] = h;
    g_wb_lo[idx] = __float2bfloat16(v - __bfloat162float(h));
}

// GEMM weights: src [128 k][n1(+n2)] -> [kc][n:Ntot][64 ki] hi/lo (zero padded)
__global__ __launch_bounds__(256) void prep_wsplit(
    const float* __restrict__ w1, int n1, const float* __restrict__ w2, int n2,
    int Ntot, __nv_bfloat16* __restrict__ dhi, __nv_bfloat16* __restrict__ dlo)
{
    int idx = blockIdx.x*256 + threadIdx.x;
    if (idx >= 2*Ntot*64) return;
    int ki = idx & 63;
    int n  = (idx >> 6) % Ntot;
    int kc = idx / (64*Ntot);
    int k  = kc*64 + ki;
    float v = 0.f;
    if (n < n1)           v = w1[(size_t)k*n1 + n];
    else if (n < n1 + n2) v = w2[(size_t)k*n2 + (n - n1)];
    __nv_bfloat16 h = __float2bfloat16(v);
    dhi[idx] = h;
    dlo[idx] = __float2bfloat16(v - __bfloat162float(h));
}

// ===================== conv1 via mma.sync bf16 hi/lo =====================
__global__ __launch_bounds__(256) void conv1_mma(
    const float* __restrict__ bg, const float* __restrict__ bb,
    const float* __restrict__ bm, const float* __restrict__ bv)
{
    extern __shared__ char smraw[];
    char* smA = smraw + ((1024 - (smem_to_u32(smraw) & 1023)) & 1023);
    const uint32_t sb = smem_to_u32(smA);
    __shared__ float s_sc[128], s_sh[128];

    const int t = threadIdx.x, wid = t >> 5, lane = t & 31;
    const int img = blockIdx.x / 28, oy0 = (blockIdx.x % 28) * 2;

    if (t < 128) {
        float inv = rsqrtf(bv[t] + EPSS);
        float sc = bg[t]*inv;
        s_sc[t] = sc; s_sh[t] = bb[t] - bm[t]*sc;
    }

    const int col16 = t & 7;
    const int r0    = t >> 3;
    auto issue = [&](int j, int d) {
        int tap = j >> 2, cc = j & 3;
        int ky = tap / 3, kx = tap - ky*3;
        uint32_t st = sb + d*STGB;
        size_t xoff = (((size_t)(img*58 + oy0 + ky))*XPW + kx)*256 + cc*64 + col16*8;
        const __nv_bfloat16* axh = g_xp_hi + xoff;
        const __nv_bfloat16* axl = g_xp_lo + xoff;
        const __nv_bfloat16* bwh = g_wb_hi + (size_t)j*8192 + col16*8;
        const __nv_bfloat16* bwl = g_wb_lo + (size_t)j*8192 + col16*8;
        #pragma unroll
        for (int jj = 0; jj < 4; jj++) {
            int m = r0 + 32*jj;
            uint32_t so = SWZ128((uint32_t)(m*128 + col16*16));
            size_t ga = ((size_t)(m >> 6))*(XPW*256) + (size_t)(m & 63)*256;
            CP_ASYNC16(st +         so, axh + ga);
            CP_ASYNC16(st + 16384 + so, axl + ga);
            CP_ASYNC16(st + 32768 + so, bwh + (size_t)m*64);
            CP_ASYNC16(st + 49152 + so, bwl + (size_t)m*64);
        }
        asm volatile("cp.async.commit_group;" ::: "memory");
    };

    const int wm = wid & 3, wn = wid >> 2;
    float acc[2][8][4];
    #pragma unroll
    for (int a = 0; a < 2; a++)
        #pragma unroll
        for (int b = 0; b < 8; b++)
            #pragma unroll
            for (int c = 0; c < 4; c++) acc[a][b][c] = 0.f;

    const int lg = lane >> 3, lri = lane & 7;
    const int rsel = (lg & 1)*8 + lri;
    const int csel = (lg >> 1)*16;

    issue(0, 0); issue(1, 1);
    for (int i = 0; i < NCHUNK; i++) {
        if (i < NCHUNK-1) asm volatile("cp.async.wait_group 1;" ::: "memory");
        else              asm volatile("cp.async.wait_group 0;" ::: "memory");
        __syncthreads();
        if (i + 2 < NCHUNK) issue(i + 2, (i + 2) % NSTG);

        uint32_t base = sb + (i % NSTG)*STGB;
        #pragma unroll
        for (int ks = 0; ks < 4; ks++) {
            int cb = ks*32 + csel;
            uint32_t ah[2][4], al[2][4], bbf[4][4];
            #pragma unroll
            for (int mf = 0; mf < 2; mf++) {
                int row = wm*32 + mf*16 + rsel;
                ldsm4(ah[mf], base + SWZ128((uint32_t)(row*128 + cb)));
            }
            #pragma unroll
            for (int nb = 0; nb < 4; nb++) {
                int row = wn*64 + nb*16 + rsel;
                ldsm4(bbf[nb], base + 32768 + SWZ128((uint32_t)(row*128 + cb)));
            }
            #pragma unroll
            for (int mf = 0; mf < 2; mf++)
                #pragma unroll
                for (int nf = 0; nf < 8; nf++)
                    mma16816(acc[mf][nf], ah[mf], bbf[nf>>1][nf&1], bbf[nf>>1][(nf&1)+2]);
            #pragma unroll
            for (int mf = 0; mf < 2; mf++) {
                int row = wm*32 + mf*16 + rsel;
                ldsm4(al[mf], base + 16384 + SWZ128((uint32_t)(row*128 + cb)));
            }
            #pragma unroll
            for (int mf = 0; mf < 2; mf++)
                #pragma unroll
                for (int nf = 0; nf < 8; nf++)
                    mma16816(acc[mf][nf], al[mf], bbf[nf>>1][nf&1], bbf[nf>>1][(nf&1)+2]);
            #pragma unroll
            for (int nb = 0; nb < 4; nb++) {
                int row = wn*64 + nb*16 + rsel;
                ldsm4(bbf[nb], base + 49152 + SWZ128((uint32_t)(row*128 + cb)));
            }
            #pragma unroll
            for (int mf = 0; mf < 2; mf++)
                #pragma unroll
                for (int nf = 0; nf < 8; nf++)
                    mma16816(acc[mf][nf], ah[mf], bbf[nf>>1][nf&1], bbf[nf>>1][(nf&1)+2]);
        }
    }

    // epilogue: BN + SiLU; fp32 NHWC store + bf16 hi/lo store for value GEMM
    const int ro = lane >> 2, co = (lane & 3) << 1;
    #pragma unroll
    for (int mf = 0; mf < 2; mf++) {
        #pragma unroll
        for (int half = 0; half < 2; half++) {
            int m = wm*32 + mf*16 + half*8 + ro;
            int ox = m & 63, ysub = m >> 6;
            if (ox < 56) {
                size_t pidbase = ((size_t)(img*HW + (oy0 + ysub)*WW + ox))*CM;
                float* dst = g_h + pidbase;
                #pragma unroll
                for (int nf = 0; nf < 8; nf++) {
                    int c = wn*64 + nf*8 + co;
                    float2 o2;
                    o2.x = siluf(acc[mf][nf][half*2+0]*s_sc[c]   + s_sh[c]);
                    o2.y = siluf(acc[mf][nf][half*2+1]*s_sc[c+1] + s_sh[c+1]);
                    *(float2*)(dst + c) = o2;
                    __nv_bfloat162 hh, ll;
                    hh.x = __float2bfloat16(o2.x);
                    hh.y = __float2bfloat16(o2.y);
                    ll.x = __float2bfloat16(o2.x - __bfloat162float(hh.x));
                    ll.y = __float2bfloat16(o2.y - __bfloat162float(hh.y));
                    *(__nv_bfloat162*)(g_hb_hi + pidbase + c) = hh;
                    *(__nv_bfloat162*)(g_hb_lo + pidbase + c) = ll;
                }
            }
        }
    }
}

// ===================== generic K=128 GEMM on mma.sync =====================
// CTA tile M=64 x N=128, K=128 (2 chunks of 64). One-shot cp.async (96KB smem,
// 2 CTAs/SM). 8 warps 2m x 4n, warp tile 32x32, bf16 hi/lo 3-term.
// EPI 0/1: C = acc + bias(split), fp32, stride Nout (col guard for Nout<128)
// EPI 2:   out = resid + silu(bn(acc + eb)), NCHW via smem transpose
template<int EPI>
__global__ __launch_bounds__(256) void gemm_tc(
    const __nv_bfloat16* __restrict__ Ahi, const __nv_bfloat16* __restrict__ Alo,
    const __nv_bfloat16* __restrict__ Bhi, const __nv_bfloat16* __restrict__ Blo,
    int Ntot, int Nout, int N1,
    const float* __restrict__ bias, const float* __restrict__ bias2,
    float* __restrict__ C,
    const float* __restrict__ eb,
    const float* __restrict__ bg, const float* __restrict__ bb,
    const float* __restrict__ bm, const float* __restrict__ bv,
    const float* __restrict__ resid)
{
    extern __shared__ char smraw[];
    char* smA = smraw + ((1024 - (smem_to_u32(smraw) & 1023)) & 1023);
    const uint32_t sbA = smem_to_u32(smA);          // A: 32KB [buf][kc][64m][128B]
    const uint32_t sbB = sbA + 32768;               // B: 64KB [buf][kc][128n][128B]

    const int t = threadIdx.x, wid = t >> 5, lane = t & 31;
    const int m0 = blockIdx.x * 64;
    const int n0 = blockIdx.y * 128;

    // one-shot loads
    #pragma unroll
    for (int i = 0; i < 8; i++) {
        int g = t*8 + i;
        int buf = g >> 10, kc = (g >> 9) & 1, m = (g >> 3) & 63, c16 = g & 7;
        const __nv_bfloat16* src = (buf ? Alo : Ahi)
            + (size_t)(m0 + m)*128 + kc*64 + c16*8;
        CP_ASYNC16(sbA + buf*16384 + kc*8192 + SWZ128((uint32_t)(m*128 + c16*16)), src);
    }
    #pragma unroll
    for (int i = 0; i < 16; i++) {
        int g = t*16 + i;
        int buf = g >> 11, kc = (g >> 10) & 1, n = (g >> 3) & 127, c16 = g & 7;
        const __nv_bfloat16* src = (buf ? Blo : Bhi)
            + ((size_t)kc*Ntot + n0 + n)*64 + c16*8;
        CP_ASYNC16(sbB + buf*32768 + kc*16384 + SWZ128((uint32_t)(n*128 + c16*16)), src);
    }
    asm volatile("cp.async.commit_group;" ::: "memory");
    asm volatile("cp.async.wait_group 0;" ::: "memory");
    __syncthreads();

    const int wm = wid & 1, wn = wid >> 1;
    float acc[2][4][4];
    #pragma unroll
    for (int a = 0; a < 2; a++)
        #pragma unroll
        for (int b = 0; b < 4; b++)
            #pragma unroll
            for (int c = 0; c < 4; c++) acc[a][b][c] = 0.f;

    const int lg = lane >> 3, lri = lane & 7;
    const int rsel = (lg & 1)*8 + lri;
    const int csel = (lg >> 1)*16;

    #pragma unroll
    for (int kc = 0; kc < 2; kc++) {
        uint32_t aH = sbA +          kc*8192;
        uint32_t aL = sbA + 16384 +  kc*8192;
        uint32_t bH = sbB +          kc*16384;
        uint32_t bL = sbB + 32768 +  kc*16384;
        #pragma unroll
        for (int ks = 0; ks < 4; ks++) {
            int cb = ks*32 + csel;
            uint32_t ah[2][4], al[2][4], bf[2][4];
            #pragma unroll
            for (int mf = 0; mf < 2; mf++) {
                int row = wm*32 + mf*16 + rsel;
                ldsm4(ah[mf], aH + SWZ128((uint32_t)(row*128 + cb)));
            }
            #pragma unroll
            for (int nb = 0; nb < 2; nb++) {
                int row = wn*32 + nb*16 + rsel;
                ldsm4(bf[nb], bH + SWZ128((uint32_t)(row*128 + cb)));
            }
            #pragma unroll
            for (int mf = 0; mf < 2; mf++)
                #pragma unroll
                for (int nf = 0; nf < 4; nf++)
                    mma16816(acc[mf][nf], ah[mf], bf[nf>>1][nf&1], bf[nf>>1][(nf&1)+2]);
            #pragma unroll
            for (int mf = 0; mf < 2; mf++) {
                int row = wm*32 + mf*16 + rsel;
                ldsm4(al[mf], aL + SWZ128((uint32_t)(row*128 + cb)));
            }
            #pragma unroll
            for (int mf = 0; mf < 2; mf++)
                #pragma unroll
                for (int nf = 0; nf < 4; nf++)
                    mma16816(acc[mf][nf], al[mf], bf[nf>>1][nf&1], bf[nf>>1][(nf&1)+2]);
            #pragma unroll
            for (int nb = 0; nb < 2; nb++) {
                int row = wn*32 + nb*16 + rsel;
                ldsm4(bf[nb], bL + SWZ128((uint32_t)(row*128 + cb)));
            }
            #pragma unroll
            for (int mf = 0; mf < 2; mf++)
                #pragma unroll
                for (int nf = 0; nf < 4; nf++)
                    mma16816(acc[mf][nf], ah[mf], bf[nf>>1][nf&1], bf[nf>>1][(nf&1)+2]);
        }
    }

    const int ro = lane >> 2, co = (lane & 3) << 1;
    if (EPI != 2) {
        #pragma unroll
        for (int mf = 0; mf < 2; mf++) {
            #pragma unroll
            for (int half = 0; half < 2; half++) {
                int m = wm*32 + mf*16 + half*8 + ro;
                size_t rowb = (size_t)(m0 + m)*Nout;
                #pragma unroll
                for (int nf = 0; nf < 4; nf++) {
                    int c = n0 + wn*32 + nf*8 + co;
                    if (c < Nout) {
                        float b0 = (c   < N1) ? bias[c]   : ((c   < Nout) ? bias2[c-N1]   : 0.f);
                        float b1 = (c+1 < N1) ? bias[c+1] : ((c+1 < Nout) ? bias2[c+1-N1] : 0.f);
                        float2 o2;
                        o2.x = acc[mf][nf][half*2+0] + b0;
                        o2.y = acc[mf][nf][half*2+1] + b1;
                        *(float2*)(C + rowb + c) = o2;
                    }
                }
            }
        }
    } else {
        __syncthreads();
        float* st = (float*)smA;   // reuse smem: [128 n][66 pitch] fp32
        #pragma unroll
        for (int mf = 0; mf < 2; mf++) {
            #pragma unroll
            for (int half = 0; half < 2; half++) {
                int m = wm*32 + mf*16 + half*8 + ro;
                #pragma unroll
                for (int nf = 0; nf < 4; nf++) {
                    int cl = wn*32 + nf*8 + co;
                    int c  = n0 + cl;
                    float inv0 = rsqrtf(bv[c] + EPSS);
                    float sc0  = bg[c]*inv0;
                    float v0 = (acc[mf][nf][half*2+0] + eb[c])*sc0 + (bb[c] - bm[c]*sc0);
                    float inv1 = rsqrtf(bv[c+1] + EPSS);
                    float sc1  = bg[c+1]*inv1;
                    float v1 = (acc[mf][nf][half*2+1] + eb[c+1])*sc1 + (bb[c+1] - bm[c+1]*sc1);
                    st[cl*66 + m]     = siluf(v0);
                    st[(cl+1)*66 + m] = siluf(v1);
                }
            }
        }
        __syncthreads();
        const int mloc = t & 63, nsub = t >> 6;
        const int mg = m0 + mloc;
        const int img = mg / HW;
        const int pp  = mg - img*HW;
        const size_t ob = (size_t)img*C2*HW + pp;
        #pragma unroll
        for (int i = 0; i < 32; i++) {
            int n = nsub + i*4;
            size_t adr = ob + (size_t)(n0 + n)*HW;
            C[adr] = resid[adr] + st[n*66 + mloc];
        }
    }
}

// ===================== depthwise + LN + GELU =====================
__global__ __launch_bounds__(128) void dw_ln_gelu(
    const float* __restrict__ wdw, const float* __restrict__ bdw,
    const float* __restrict__ lg,  const float* __restrict__ lb)
{
    const int pix = blockIdx.x;
    const int c   = threadIdx.x;
    const int img = pix / HW;
    const int p   = pix - img*HW;
    const int py  = p / WW;
    const int px  = p - py*WW;
    const float* hb = g_h + (size_t)img*HW*CM;

    float s = bdw[c];
    #pragma unroll
    for (int ky = 0; ky < 3; ky++) {
        int yy = py + ky - 1;
        if ((unsigned)yy >= HH) continue;
        #pragma unroll
        for (int kx = 0; kx < 3; kx++) {
            int xx = px + kx - 1;
            if ((unsigned)xx >= WW) continue;
            s = fmaf(hb[(size_t)(yy*WW + xx)*CM + c], wdw[c*9 + ky*3 + kx], s);
        }
    }
    float r1 = s, r2 = s*s;
    #pragma unroll
    for (int o = 16; o; o >>= 1) {
        r1 += __shfl_xor_sync(0xffffffffu, r1, o);
        r2 += __shfl_xor_sync(0xffffffffu, r2, o);
    }
    __shared__ float rb[8];
    int wi = c >> 5;
    if ((c & 31) == 0) { rb[wi] = r1; rb[4+wi] = r2; }
    __syncthreads();
    float sum = rb[0]+rb[1]+rb[2]+rb[3];
    float ssq = rb[4]+rb[5]+rb[6]+rb[7];
    float mu  = sum * (1.f/CM);
    float var = ssq * (1.f/CM) - mu*mu;
    float tn  = (s - mu) * rsqrtf(var + EPSS) * lg[c] + lb[c];
    float ge  = 0.5f * tn * (1.f + erff(tn * 0.70710678118654752f));
    __nv_bfloat16 h = __float2bfloat16(ge);
    g_tb_hi[(size_t)pix*CM + c] = h;
    g_tb_lo[(size_t)pix*CM + c] = __float2bfloat16(ge - __bfloat162float(h));
}

// ===================== DCNv3 sampler =====================
__global__ __launch_bounds__(256) void dcn_core()
{
    int gw   = (blockIdx.x*blockDim.x + threadIdx.x) >> 5;
    int lane = threadIdx.x & 31;
    if (gw >= NPIX*GG) return;
    int pid = gw >> 2;
    int g   = gw & 3;
    int img = pid / HW;
    int p   = pid - img*HW;
    int iy  = p / WW;
    int ix  = p - iy*WW;

    const float* om = g_om + (size_t)pid*NOM;
    float m9[9]; float mx = -1e30f;
    #pragma unroll
    for (int k = 0; k < 9; k++) { m9[k] = om[72 + g*9 + k]; mx = fmaxf(mx, m9[k]); }
    float se = 0.f;
    #pragma unroll
    for (int k = 0; k < 9; k++) { m9[k] = expf(m9[k] - mx); se += m9[k]; }
    float inv = 1.f / se;

    const float* vb = g_v + (size_t)img*HW*CM + g*GC + lane;
    float acc = 0.f;
    #pragma unroll
    for (int k = 0; k < 9; k++) {
        float dx = om[(g*9 + k)*2];
        float dy = om[(g*9 + k)*2 + 1];
        int kxi = k / 3;
        int kyi = k - kxi*3;
        float fx = (float)(ix + kxi) + dx;
        float fy = (float)(iy + kyi) + dy;
        float x0f = floorf(fx), y0f = floorf(fy);
        float wx = fx - x0f, wy = fy - y0f;
        int xm = (int)x0f - 1, ym = (int)y0f - 1;
        float v00 = 0.f, v01 = 0.f, v10 = 0.f, v11 = 0.f;
        bool vx0 = (unsigned)xm     < WW;
        bool vx1 = (unsigned)(xm+1) < WW;
        bool vy0 = (unsigned)ym     < HH;
        bool vy1 = (unsigned)(ym+1) < HH;
        if (vy0 && vx0) v00 = vb[(size_t)(ym*WW + xm      )*CM];
        if (vy0 && vx1) v01 = vb[(size_t)(ym*WW + xm + 1  )*CM];
        if (vy1 && vx0) v10 = vb[(size_t)((ym+1)*WW + xm  )*CM];
        if (vy1 && vx1) v11 = vb[(size_t)((ym+1)*WW + xm+1)*CM];
        float sv = v00*(1.f-wy)*(1.f-wx) + v01*(1.f-wy)*wx
                 + v10*wy*(1.f-wx)       + v11*wy*wx;
        acc = fmaf(m9[k]*inv, sv, acc);
    }
    size_t oidx = (size_t)pid*CM + g*GC + lane;
    __nv_bfloat16 h = __float2bfloat16(acc);
    g_ob_hi[oidx] = h;
    g_ob_lo[oidx] = __float2bfloat16(acc - __bfloat162float(h));
}

// ===================== launch =====================
extern "C" void kernel_launch(void* const* d_in, const int* in_sizes, int n_in,
                              void* d_out, int out_size)
{
    const float* x    = (const float*)d_in[0];
    const float* wcv1 = (const float*)d_in[1];
    const float* bn1g = (const float*)d_in[2];
    const float* bn1b = (const float*)d_in[3];
    const float* bn1m = (const float*)d_in[4];
    const float* bn1v = (const float*)d_in[5];
    const float* wdw  = (const float*)d_in[6];
    const float* bdw  = (const float*)d_in[7];
    const float* lng  = (const float*)d_in[8];
    const float* lnb  = (const float*)d_in[9];
    const float* winp = (const float*)d_in[10];
    const float* binp = (const float*)d_in[11];
    const float* woff = (const float*)d_in[12];
    const float* boff = (const float*)d_in[13];
    const float* wmsk = (const float*)d_in[14];
    const float* bmsk = (const float*)d_in[15];
    const float* wout = (const float*)d_in[16];
    const float* bout = (const float*)d_in[17];
    const float* bn2g = (const float*)d_in[18];
    const float* bn2b = (const float*)d_in[19];
    const float* bn2m = (const float*)d_in[20];
    const float* bn2v = (const float*)d_in[21];
    float* out = (float*)d_out;

    float *pv, *pom;
    cudaGetSymbolAddress((void**)&pv,  g_v);
    cudaGetSymbolAddress((void**)&pom, g_om);
    __nv_bfloat16 *hbh, *hbl, *tbh, *tbl, *obh, *obl;
    __nv_bfloat16 *wvh, *wvl, *womh, *woml, *woh, *wol;
    cudaGetSymbolAddress((void**)&hbh, g_hb_hi); cudaGetSymbolAddress((void**)&hbl, g_hb_lo);
    cudaGetSymbolAddress((void**)&tbh, g_tb_hi); cudaGetSymbolAddress((void**)&tbl, g_tb_lo);
    cudaGetSymbolAddress((void**)&obh, g_ob_hi); cudaGetSymbolAddress((void**)&obl, g_ob_lo);
    cudaGetSymbolAddress((void**)&wvh, g_wv_hi); cudaGetSymbolAddress((void**)&wvl, g_wv_lo);
    cudaGetSymbolAddress((void**)&womh, g_wom_hi); cudaGetSymbolAddress((void**)&woml, g_wom_lo);
    cudaGetSymbolAddress((void**)&woh, g_wo_hi); cudaGetSymbolAddress((void**)&wol, g_wo_lo);

    const int smem_conv = NSTG*STGB + 1024;
    const int smem_gemm = 96*1024 + 1024;
    cudaFuncSetAttribute(conv1_mma, cudaFuncAttributeMaxDynamicSharedMemorySize, smem_conv);
    cudaFuncSetAttribute(gemm_tc<0>, cudaFuncAttributeMaxDynamicSharedMemorySize, smem_gemm);
    cudaFuncSetAttribute(gemm_tc<1>, cudaFuncAttributeMaxDynamicSharedMemorySize, smem_gemm);
    cudaFuncSetAttribute(gemm_tc<2>, cudaFuncAttributeMaxDynamicSharedMemorySize, smem_gemm);

    xprep<<<8*58, 256>>>(x);
    wprep<<<(NCHUNK*128*64 + 255)/256, 256>>>(wcv1);
    prep_wsplit<<<64, 256>>>(winp, 128, nullptr, 0, 128, wvh, wvl);
    prep_wsplit<<<64, 256>>>(woff, 72, wmsk, 36, 128, womh, woml);
    prep_wsplit<<<128, 256>>>(wout, 256, nullptr, 0, 256, woh, wol);

    conv1_mma<<<8*28, 256, smem_conv>>>(bn1g, bn1b, bn1m, bn1v);
    dw_ln_gelu<<<NPIX, 128>>>(wdw, bdw, lng, lnb);

    // value projection -> g_v (fp32, dcn reads it)
    gemm_tc<0><<<dim3(NPIX/64, 1), 256, smem_gemm>>>(hbh, hbl, wvh, wvl,
        128, 128, 128, binp, nullptr, pv,
        nullptr, nullptr, nullptr, nullptr, nullptr, nullptr);
    // offsets + mask logits -> g_om
    gemm_tc<1><<<dim3(NPIX/64, 1), 256, smem_gemm>>>(tbh, tbl, womh, woml,
        128, NOM, 72, boff, bmsk, pom,
        nullptr, nullptr, nullptr, nullptr, nullptr, nullptr);
    // deformable sampling -> g_ob hi/lo
    dcn_core<<<(NPIX*GG)/8, 256>>>();
    // output projection + BN + SiLU + residual -> out (NCHW)
    gemm_tc<2><<<dim3(NPIX/64, 2), 256, smem_gemm>>>(obh, obl, woh, wol,
        256, 256, 256, nullptr, nullptr, out,
        bout, bn2g, bn2b, bn2m, bn2v, x);
}

// round 6
// speedup vs baseline: 2.0367x; 1.0383x over previous
#include <cuda_runtime.h>
#include <cuda_bf16.h>
#include <math.h>
#include <stdint.h>

#define NB   8
#define C1   256
#define C2   256
#define CM   128
#define HH   56
#define WW   56
#define HW   3136
#define NPIX (NB*HW)
#define GG   4
#define GC   32
#define EPSS 1e-5f
#define NOM  108
#define NCHUNK 36
#define NSTG 3
#define XPW  66
#define STGB 65536

// scratch (device globals: allocation-free rule)
__device__ float g_h [NPIX*CM];
__device__ float g_v [NPIX*CM];
__device__ float g_om[NPIX*NOM];
__device__ __nv_bfloat16 g_xp_hi[8*58*XPW*256];
__device__ __nv_bfloat16 g_xp_lo[8*58*XPW*256];
__device__ __nv_bfloat16 g_wb_hi[NCHUNK*128*64];
__device__ __nv_bfloat16 g_wb_lo[NCHUNK*128*64];
// bf16 hi/lo A-operands for the K=128 GEMMs
__device__ __nv_bfloat16 g_hb_hi[NPIX*CM], g_hb_lo[NPIX*CM];
__device__ __nv_bfloat16 g_tb_hi[NPIX*CM], g_tb_lo[NPIX*CM];
__device__ __nv_bfloat16 g_ob_hi[NPIX*CM], g_ob_lo[NPIX*CM];
// B operands, layout [kc(2)][n][64 k], k-major rows
__device__ __nv_bfloat16 g_wv_hi [2*128*64], g_wv_lo [2*128*64];
__device__ __nv_bfloat16 g_wom_hi[2*128*64], g_wom_lo[2*128*64];
__device__ __nv_bfloat16 g_wo_hi [2*256*64], g_wo_lo [2*256*64];

__device__ __forceinline__ float siluf(float v){ return v / (1.f + expf(-v)); }

__device__ __forceinline__ uint32_t smem_to_u32(const void* p) {
    uint32_t a;
    asm("{ .reg .u64 t; cvta.to.shared.u64 t, %1; cvt.u32.u64 %0, t; }" : "=r"(a) : "l"(p));
    return a;
}
#define SWZ128(o) ((o) ^ (((o) >> 3) & 0x70))
#define CP_ASYNC16(sa, gp) \
    asm volatile("cp.async.cg.shared.global [%0], [%1], 16;" \
        :: "r"((uint32_t)(sa)), "l"(gp) : "memory")

__device__ __forceinline__ void ldsm4(uint32_t* r, uint32_t addr) {
    asm volatile("ldmatrix.sync.aligned.m8n8.x4.shared.b16 {%0,%1,%2,%3}, [%4];"
        : "=r"(r[0]), "=r"(r[1]), "=r"(r[2]), "=r"(r[3]) : "r"(addr));
}
__device__ __forceinline__ void mma16816(float* d, const uint32_t* a, uint32_t b0, uint32_t b1) {
    asm volatile("mma.sync.aligned.m16n8k16.row.col.f32.bf16.bf16.f32 "
        "{%0,%1,%2,%3}, {%4,%5,%6,%7}, {%8,%9}, {%0,%1,%2,%3};"
        : "+f"(d[0]), "+f"(d[1]), "+f"(d[2]), "+f"(d[3])
        : "r"(a[0]), "r"(a[1]), "r"(a[2]), "r"(a[3]), "r"(b0), "r"(b1));
}

// ===================== prep: pad/transpose/split x =====================
__global__ __launch_bounds__(256) void xprep(const float* __restrict__ x)
{
    const int b = blockIdx.x, img = b / 58, yp = b % 58;
    const size_t rowbase = ((size_t)img*58 + yp) * (XPW*256);
    const int t = threadIdx.x;
    uint2 z2 = make_uint2(0u, 0u);
    for (int i = t; i < XPW*256/4; i += 256) {
        ((uint2*)(g_xp_hi + rowbase))[i] = z2;
        ((uint2*)(g_xp_lo + rowbase))[i] = z2;
    }
    if (yp == 0 || yp == 57) return;
    __syncthreads();
    const int oy = yp - 1;
    __shared__ float sm[128*57];
    for (int pass = 0; pass < 2; pass++) {
        for (int i = t; i < 128*56; i += 256) {
            int c = i / 56, ox = i % 56;
            sm[c*57 + ox] = x[((size_t)(img*256 + pass*128 + c))*HW + oy*WW + ox];
        }
        __syncthreads();
        for (int i = t; i < 56*128; i += 256) {
            int ox = i >> 7, c = i & 127;
            float v = sm[c*57 + ox];
            __nv_bfloat16 h = __float2bfloat16(v);
            size_t a = rowbase + (size_t)(ox+1)*256 + pass*128 + c;
            g_xp_hi[a] = h;
            g_xp_lo[a] = __float2bfloat16(v - __bfloat162float(h));
        }
        __syncthreads();
    }
}

// conv weights: w[o][c*9+tap] -> [chunk=tap*4+cc][o][ci]
__global__ __launch_bounds__(256) void wprep(const float* __restrict__ w)
{
    int idx = blockIdx.x*256 + threadIdx.x;
    if (idx >= NCHUNK*128*64) return;
    int ci = idx & 63, o = (idx >> 6) & 127, ch = idx >> 13;
    int tap = ch >> 2, cc = ch & 3;
    float v = w[(size_t)o*2304 + (cc*64 + ci)*9 + tap];
    __nv_bfloat16 h = __float2bfloat16(v);
    g_wb_hi[idx] = h;
    g_wb_lo[idx] = __float2bfloat16(v - __bfloat162float(h));
}

// GEMM weights: src [128 k][n1(+n2)] -> [kc][n:Ntot][64 ki] hi/lo (zero padded)
__global__ __launch_bounds__(256) void prep_wsplit(
    const float* __restrict__ w1, int n1, const float* __restrict__ w2, int n2,
    int Ntot, __nv_bfloat16* __restrict__ dhi, __nv_bfloat16* __restrict__ dlo)
{
    int idx = blockIdx.x*256 + threadIdx.x;
    if (idx >= 2*Ntot*64) return;
    int ki = idx & 63;
    int n  = (idx >> 6) % Ntot;
    int kc = idx / (64*Ntot);
    int k  = kc*64 + ki;
    float v = 0.f;
    if (n < n1)           v = w1[(size_t)k*n1 + n];
    else if (n < n1 + n2) v = w2[(size_t)k*n2 + (n - n1)];
    __nv_bfloat16 h = __float2bfloat16(v);
    dhi[idx] = h;
    dlo[idx] = __float2bfloat16(v - __bfloat162float(h));
}

// ===================== conv1 via mma.sync bf16 hi/lo =====================
__global__ __launch_bounds__(256) void conv1_mma(
    const float* __restrict__ bg, const float* __restrict__ bb,
    const float* __restrict__ bm, const float* __restrict__ bv)
{
    extern __shared__ char smraw[];
    char* smA = smraw + ((1024 - (smem_to_u32(smraw) & 1023)) & 1023);
    const uint32_t sb = smem_to_u32(smA);
    __shared__ float s_sc[128], s_sh[128];

    const int t = threadIdx.x, wid = t >> 5, lane = t & 31;
    const int img = blockIdx.x / 28, oy0 = (blockIdx.x % 28) * 2;

    if (t < 128) {
        float inv = rsqrtf(bv[t] + EPSS);
        float sc = bg[t]*inv;
        s_sc[t] = sc; s_sh[t] = bb[t] - bm[t]*sc;
    }

    const int col16 = t & 7;
    const int r0    = t >> 3;
    auto issue = [&](int j, int d) {
        int tap = j >> 2, cc = j & 3;
        int ky = tap / 3, kx = tap - ky*3;
        uint32_t st = sb + d*STGB;
        size_t xoff = (((size_t)(img*58 + oy0 + ky))*XPW + kx)*256 + cc*64 + col16*8;
        const __nv_bfloat16* axh = g_xp_hi + xoff;
        const __nv_bfloat16* axl = g_xp_lo + xoff;
        const __nv_bfloat16* bwh = g_wb_hi + (size_t)j*8192 + col16*8;
        const __nv_bfloat16* bwl = g_wb_lo + (size_t)j*8192 + col16*8;
        #pragma unroll
        for (int jj = 0; jj < 4; jj++) {
            int m = r0 + 32*jj;
            uint32_t so = SWZ128((uint32_t)(m*128 + col16*16));
            size_t ga = ((size_t)(m >> 6))*(XPW*256) + (size_t)(m & 63)*256;
            CP_ASYNC16(st +         so, axh + ga);
            CP_ASYNC16(st + 16384 + so, axl + ga);
            CP_ASYNC16(st + 32768 + so, bwh + (size_t)m*64);
            CP_ASYNC16(st + 49152 + so, bwl + (size_t)m*64);
        }
        asm volatile("cp.async.commit_group;" ::: "memory");
    };

    const int wm = wid & 3, wn = wid >> 2;
    float acc[2][8][4];
    #pragma unroll
    for (int a = 0; a < 2; a++)
        #pragma unroll
        for (int b = 0; b < 8; b++)
            #pragma unroll
            for (int c = 0; c < 4; c++) acc[a][b][c] = 0.f;

    const int lg = lane >> 3, lri = lane & 7;
    const int rsel = (lg & 1)*8 + lri;
    const int csel = (lg >> 1)*16;

    issue(0, 0); issue(1, 1);
    for (int i = 0; i < NCHUNK; i++) {
        if (i < NCHUNK-1) asm volatile("cp.async.wait_group 1;" ::: "memory");
        else              asm volatile("cp.async.wait_group 0;" ::: "memory");
        __syncthreads();
        if (i + 2 < NCHUNK) issue(i + 2, (i + 2) % NSTG);

        uint32_t base = sb + (i % NSTG)*STGB;
        #pragma unroll
        for (int ks = 0; ks < 4; ks++) {
            int cb = ks*32 + csel;
            uint32_t ah[2][4], al[2][4], bbf[4][4];
            #pragma unroll
            for (int mf = 0; mf < 2; mf++) {
                int row = wm*32 + mf*16 + rsel;
                ldsm4(ah[mf], base + SWZ128((uint32_t)(row*128 + cb)));
            }
            #pragma unroll
            for (int nb = 0; nb < 4; nb++) {
                int row = wn*64 + nb*16 + rsel;
                ldsm4(bbf[nb], base + 32768 + SWZ128((uint32_t)(row*128 + cb)));
            }
            #pragma unroll
            for (int mf = 0; mf < 2; mf++)
                #pragma unroll
                for (int nf = 0; nf < 8; nf++)
                    mma16816(acc[mf][nf], ah[mf], bbf[nf>>1][nf&1], bbf[nf>>1][(nf&1)+2]);
            #pragma unroll
            for (int mf = 0; mf < 2; mf++) {
                int row = wm*32 + mf*16 + rsel;
                ldsm4(al[mf], base + 16384 + SWZ128((uint32_t)(row*128 + cb)));
            }
            #pragma unroll
            for (int mf = 0; mf < 2; mf++)
                #pragma unroll
                for (int nf = 0; nf < 8; nf++)
                    mma16816(acc[mf][nf], al[mf], bbf[nf>>1][nf&1], bbf[nf>>1][(nf&1)+2]);
            #pragma unroll
            for (int nb = 0; nb < 4; nb++) {
                int row = wn*64 + nb*16 + rsel;
                ldsm4(bbf[nb], base + 49152 + SWZ128((uint32_t)(row*128 + cb)));
            }
            #pragma unroll
            for (int mf = 0; mf < 2; mf++)
                #pragma unroll
                for (int nf = 0; nf < 8; nf++)
                    mma16816(acc[mf][nf], ah[mf], bbf[nf>>1][nf&1], bbf[nf>>1][(nf&1)+2]);
        }
    }

    // epilogue: BN + SiLU; fp32 NHWC store + bf16 hi/lo store for value GEMM
    const int ro = lane >> 2, co = (lane & 3) << 1;
    #pragma unroll
    for (int mf = 0; mf < 2; mf++) {
        #pragma unroll
        for (int half = 0; half < 2; half++) {
            int m = wm*32 + mf*16 + half*8 + ro;
            int ox = m & 63, ysub = m >> 6;
            if (ox < 56) {
                size_t pidbase = ((size_t)(img*HW + (oy0 + ysub)*WW + ox))*CM;
                float* dst = g_h + pidbase;
                #pragma unroll
                for (int nf = 0; nf < 8; nf++) {
                    int c = wn*64 + nf*8 + co;
                    float2 o2;
                    o2.x = siluf(acc[mf][nf][half*2+0]*s_sc[c]   + s_sh[c]);
                    o2.y = siluf(acc[mf][nf][half*2+1]*s_sc[c+1] + s_sh[c+1]);
                    *(float2*)(dst + c) = o2;
                    __nv_bfloat162 hh, ll;
                    hh.x = __float2bfloat16(o2.x);
                    hh.y = __float2bfloat16(o2.y);
                    ll.x = __float2bfloat16(o2.x - __bfloat162float(hh.x));
                    ll.y = __float2bfloat16(o2.y - __bfloat162float(hh.y));
                    *(__nv_bfloat162*)(g_hb_hi + pidbase + c) = hh;
                    *(__nv_bfloat162*)(g_hb_lo + pidbase + c) = ll;
                }
            }
        }
    }
}

// ===================== generic K=128 GEMM on mma.sync =====================
template<int EPI>
__global__ __launch_bounds__(256) void gemm_tc(
    const __nv_bfloat16* __restrict__ Ahi, const __nv_bfloat16* __restrict__ Alo,
    const __nv_bfloat16* __restrict__ Bhi, const __nv_bfloat16* __restrict__ Blo,
    int Ntot, int Nout, int N1,
    const float* __restrict__ bias, const float* __restrict__ bias2,
    float* __restrict__ C,
    const float* __restrict__ eb,
    const float* __restrict__ bg, const float* __restrict__ bb,
    const float* __restrict__ bm, const float* __restrict__ bv,
    const float* __restrict__ resid)
{
    extern __shared__ char smraw[];
    char* smA = smraw + ((1024 - (smem_to_u32(smraw) & 1023)) & 1023);
    const uint32_t sbA = smem_to_u32(smA);
    const uint32_t sbB = sbA + 32768;

    const int t = threadIdx.x, wid = t >> 5, lane = t & 31;
    const int m0 = blockIdx.x * 64;
    const int n0 = blockIdx.y * 128;

    #pragma unroll
    for (int i = 0; i < 8; i++) {
        int g = t*8 + i;
        int buf = g >> 10, kc = (g >> 9) & 1, m = (g >> 3) & 63, c16 = g & 7;
        const __nv_bfloat16* src = (buf ? Alo : Ahi)
            + (size_t)(m0 + m)*128 + kc*64 + c16*8;
        CP_ASYNC16(sbA + buf*16384 + kc*8192 + SWZ128((uint32_t)(m*128 + c16*16)), src);
    }
    #pragma unroll
    for (int i = 0; i < 16; i++) {
        int g = t*16 + i;
        int buf = g >> 11, kc = (g >> 10) & 1, n = (g >> 3) & 127, c16 = g & 7;
        const __nv_bfloat16* src = (buf ? Blo : Bhi)
            + ((size_t)kc*Ntot + n0 + n)*64 + c16*8;
        CP_ASYNC16(sbB + buf*32768 + kc*16384 + SWZ128((uint32_t)(n*128 + c16*16)), src);
    }
    asm volatile("cp.async.commit_group;" ::: "memory");
    asm volatile("cp.async.wait_group 0;" ::: "memory");
    __syncthreads();

    const int wm = wid & 1, wn = wid >> 1;
    float acc[2][4][4];
    #pragma unroll
    for (int a = 0; a < 2; a++)
        #pragma unroll
        for (int b = 0; b < 4; b++)
            #pragma unroll
            for (int c = 0; c < 4; c++) acc[a][b][c] = 0.f;

    const int lg = lane >> 3, lri = lane & 7;
    const int rsel = (lg & 1)*8 + lri;
    const int csel = (lg >> 1)*16;

    #pragma unroll
    for (int kc = 0; kc < 2; kc++) {
        uint32_t aH = sbA +          kc*8192;
        uint32_t aL = sbA + 16384 +  kc*8192;
        uint32_t bH = sbB +          kc*16384;
        uint32_t bL = sbB + 32768 +  kc*16384;
        #pragma unroll
        for (int ks = 0; ks < 4; ks++) {
            int cb = ks*32 + csel;
            uint32_t ah[2][4], al[2][4], bf[2][4];
            #pragma unroll
            for (int mf = 0; mf < 2; mf++) {
                int row = wm*32 + mf*16 + rsel;
                ldsm4(ah[mf], aH + SWZ128((uint32_t)(row*128 + cb)));
            }
            #pragma unroll
            for (int nb = 0; nb < 2; nb++) {
                int row = wn*32 + nb*16 + rsel;
                ldsm4(bf[nb], bH + SWZ128((uint32_t)(row*128 + cb)));
            }
            #pragma unroll
            for (int mf = 0; mf < 2; mf++)
                #pragma unroll
                for (int nf = 0; nf < 4; nf++)
                    mma16816(acc[mf][nf], ah[mf], bf[nf>>1][nf&1], bf[nf>>1][(nf&1)+2]);
            #pragma unroll
            for (int mf = 0; mf < 2; mf++) {
                int row = wm*32 + mf*16 + rsel;
                ldsm4(al[mf], aL + SWZ128((uint32_t)(row*128 + cb)));
            }
            #pragma unroll
            for (int mf = 0; mf < 2; mf++)
                #pragma unroll
                for (int nf = 0; nf < 4; nf++)
                    mma16816(acc[mf][nf], al[mf], bf[nf>>1][nf&1], bf[nf>>1][(nf&1)+2]);
            #pragma unroll
            for (int nb = 0; nb < 2; nb++) {
                int row = wn*32 + nb*16 + rsel;
                ldsm4(bf[nb], bL + SWZ128((uint32_t)(row*128 + cb)));
            }
            #pragma unroll
            for (int mf = 0; mf < 2; mf++)
                #pragma unroll
                for (int nf = 0; nf < 4; nf++)
                    mma16816(acc[mf][nf], ah[mf], bf[nf>>1][nf&1], bf[nf>>1][(nf&1)+2]);
        }
    }

    const int ro = lane >> 2, co = (lane & 3) << 1;
    if (EPI != 2) {
        #pragma unroll
        for (int mf = 0; mf < 2; mf++) {
            #pragma unroll
            for (int half = 0; half < 2; half++) {
                int m = wm*32 + mf*16 + half*8 + ro;
                size_t rowb = (size_t)(m0 + m)*Nout;
                #pragma unroll
                for (int nf = 0; nf < 4; nf++) {
                    int c = n0 + wn*32 + nf*8 + co;
                    if (c < Nout) {
                        float b0 = (c   < N1) ? bias[c]   : ((c   < Nout) ? bias2[c-N1]   : 0.f);
                        float b1 = (c+1 < N1) ? bias[c+1] : ((c+1 < Nout) ? bias2[c+1-N1] : 0.f);
                        float2 o2;
                        o2.x = acc[mf][nf][half*2+0] + b0;
                        o2.y = acc[mf][nf][half*2+1] + b1;
                        *(float2*)(C + rowb + c) = o2;
                    }
                }
            }
        }
    } else {
        __syncthreads();
        float* st = (float*)smA;
        #pragma unroll
        for (int mf = 0; mf < 2; mf++) {
            #pragma unroll
            for (int half = 0; half < 2; half++) {
                int m = wm*32 + mf*16 + half*8 + ro;
                #pragma unroll
                for (int nf = 0; nf < 4; nf++) {
                    int cl = wn*32 + nf*8 + co;
                    int c  = n0 + cl;
                    float inv0 = rsqrtf(bv[c] + EPSS);
                    float sc0  = bg[c]*inv0;
                    float v0 = (acc[mf][nf][half*2+0] + eb[c])*sc0 + (bb[c] - bm[c]*sc0);
                    float inv1 = rsqrtf(bv[c+1] + EPSS);
                    float sc1  = bg[c+1]*inv1;
                    float v1 = (acc[mf][nf][half*2+1] + eb[c+1])*sc1 + (bb[c+1] - bm[c+1]*sc1);
                    st[cl*66 + m]     = siluf(v0);
                    st[(cl+1)*66 + m] = siluf(v1);
                }
            }
        }
        __syncthreads();
        const int mloc = t & 63, nsub = t >> 6;
        const int mg = m0 + mloc;
        const int img = mg / HW;
        const int pp  = mg - img*HW;
        const size_t ob = (size_t)img*C2*HW + pp;
        #pragma unroll
        for (int i = 0; i < 32; i++) {
            int n = nsub + i*4;
            size_t adr = ob + (size_t)(n0 + n)*HW;
            C[adr] = resid[adr] + st[n*66 + mloc];
        }
    }
}

// ===================== depthwise + LN + GELU (warp per pixel) =====================
__global__ __launch_bounds__(128) void dw_ln_gelu(
    const float* __restrict__ wdw, const float* __restrict__ bdw,
    const float* __restrict__ lg,  const float* __restrict__ lb)
{
    __shared__ float s_w[9*128];
    __shared__ float s_b[128], s_g[128], s_lb[128];
    const int t = threadIdx.x;
    #pragma unroll
    for (int i = 0; i < 9; i++) s_w[i*128 + t] = wdw[t*9 + i];
    s_b[t] = bdw[t]; s_g[t] = lg[t]; s_lb[t] = lb[t];
    __syncthreads();

    const int warp = t >> 5, lane = t & 31;
    const int pix = blockIdx.x*4 + warp;
    const int img = pix / HW;
    const int p   = pix - img*HW;
    const int py  = p / WW, px = p - py*WW;
    const float* hb = g_h + (size_t)img*HW*CM;
    const int c0 = lane << 2;

    float sx = s_b[c0], sy = s_b[c0+1], sz = s_b[c0+2], sw = s_b[c0+3];
    #pragma unroll
    for (int ky = 0; ky < 3; ky++) {
        int yy = py + ky - 1;
        if ((unsigned)yy >= HH) continue;
        #pragma unroll
        for (int kx = 0; kx < 3; kx++) {
            int xx = px + kx - 1;
            if ((unsigned)xx >= WW) continue;
            float4 v = *(const float4*)(hb + (size_t)(yy*WW + xx)*CM + c0);
            const float* wk = s_w + (ky*3 + kx)*128 + c0;
            sx = fmaf(v.x, wk[0], sx);
            sy = fmaf(v.y, wk[1], sy);
            sz = fmaf(v.z, wk[2], sz);
            sw = fmaf(v.w, wk[3], sw);
        }
    }
    float r1 = sx + sy + sz + sw;
    float r2 = sx*sx + sy*sy + sz*sz + sw*sw;
    #pragma unroll
    for (int o = 16; o; o >>= 1) {
        r1 += __shfl_xor_sync(0xffffffffu, r1, o);
        r2 += __shfl_xor_sync(0xffffffffu, r2, o);
    }
    float mu  = r1 * (1.f/CM);
    float var = r2 * (1.f/CM) - mu*mu;
    float rs  = rsqrtf(var + EPSS);
    float vv[4] = {sx, sy, sz, sw};
    __nv_bfloat162 hh[2], ll[2];
    #pragma unroll
    for (int j = 0; j < 4; j++) {
        float tn = (vv[j] - mu)*rs*s_g[c0+j] + s_lb[c0+j];
        float ge = 0.5f*tn*(1.f + erff(tn*0.70710678118654752f));
        __nv_bfloat16 h = __float2bfloat16(ge);
        ((__nv_bfloat16*)hh)[j] = h;
        ((__nv_bfloat16*)ll)[j] = __float2bfloat16(ge - __bfloat162float(h));
    }
    size_t a = (size_t)pix*CM + c0;
    *(__nv_bfloat162*)(g_tb_hi + a)     = hh[0];
    *(__nv_bfloat162*)(g_tb_hi + a + 2) = hh[1];
    *(__nv_bfloat162*)(g_tb_lo + a)     = ll[0];
    *(__nv_bfloat162*)(g_tb_lo + a + 2) = ll[1];
}

// ===================== DCNv3 sampler (warp-cooperative softmax) =====================
__global__ __launch_bounds__(256) void dcn_core()
{
    int gw   = (blockIdx.x*blockDim.x + threadIdx.x) >> 5;
    int lane = threadIdx.x & 31;
    if (gw >= NPIX*GG) return;
    int pid = gw >> 2;
    int g   = gw & 3;
    int img = pid / HW;
    int p   = pid - img*HW;
    int iy  = p / WW;
    int ix  = p - iy*WW;

    const float* om = g_om + (size_t)pid*NOM;
    // warp softmax over 9 logits: lanes 0-8 each own one
    float lgt = (lane < 9) ? om[72 + g*9 + lane] : -1e30f;
    float mx = lgt;
    #pragma unroll
    for (int o = 16; o; o >>= 1) mx = fmaxf(mx, __shfl_xor_sync(0xffffffffu, mx, o));
    float e = (lane < 9) ? expf(lgt - mx) : 0.f;
    float se = e;
    #pragma unroll
    for (int o = 16; o; o >>= 1) se += __shfl_xor_sync(0xffffffffu, se, o);
    float inv = 1.f / se;

    const float* vb = g_v + (size_t)img*HW*CM + g*GC + lane;
    float acc = 0.f;
    #pragma unroll
    for (int k = 0; k < 9; k++) {
        float mk = __shfl_sync(0xffffffffu, e, k) * inv;
        float dx = om[(g*9 + k)*2];
        float dy = om[(g*9 + k)*2 + 1];
        int kxi = k / 3;
        int kyi = k - kxi*3;
        float fx = (float)(ix + kxi) + dx;
        float fy = (float)(iy + kyi) + dy;
        float x0f = floorf(fx), y0f = floorf(fy);
        float wx = fx - x0f, wy = fy - y0f;
        int xm = (int)x0f - 1, ym = (int)y0f - 1;
        float v00 = 0.f, v01 = 0.f, v10 = 0.f, v11 = 0.f;
        bool vx0 = (unsigned)xm     < WW;
        bool vx1 = (unsigned)(xm+1) < WW;
        bool vy0 = (unsigned)ym     < HH;
        bool vy1 = (unsigned)(ym+1) < HH;
        if (vy0 && vx0) v00 = vb[(size_t)(ym*WW + xm      )*CM];
        if (vy0 && vx1) v01 = vb[(size_t)(ym*WW + xm + 1  )*CM];
        if (vy1 && vx0) v10 = vb[(size_t)((ym+1)*WW + xm  )*CM];
        if (vy1 && vx1) v11 = vb[(size_t)((ym+1)*WW + xm+1)*CM];
        float sv = v00*(1.f-wy)*(1.f-wx) + v01*(1.f-wy)*wx
                 + v10*wy*(1.f-wx)       + v11*wy*wx;
        acc = fmaf(mk, sv, acc);
    }
    size_t oidx = (size_t)pid*CM + g*GC + lane;
    __nv_bfloat16 h = __float2bfloat16(acc);
    g_ob_hi[oidx] = h;
    g_ob_lo[oidx] = __float2bfloat16(acc - __bfloat162float(h));
}

// ===================== launch =====================
extern "C" void kernel_launch(void* const* d_in, const int* in_sizes, int n_in,
                              void* d_out, int out_size)
{
    const float* x    = (const float*)d_in[0];
    const float* wcv1 = (const float*)d_in[1];
    const float* bn1g = (const float*)d_in[2];
    const float* bn1b = (const float*)d_in[3];
    const float* bn1m = (const float*)d_in[4];
    const float* bn1v = (const float*)d_in[5];
    const float* wdw  = (const float*)d_in[6];
    const float* bdw  = (const float*)d_in[7];
    const float* lng  = (const float*)d_in[8];
    const float* lnb  = (const float*)d_in[9];
    const float* winp = (const float*)d_in[10];
    const float* binp = (const float*)d_in[11];
    const float* woff = (const float*)d_in[12];
    const float* boff = (const float*)d_in[13];
    const float* wmsk = (const float*)d_in[14];
    const float* bmsk = (const float*)d_in[15];
    const float* wout = (const float*)d_in[16];
    const float* bout = (const float*)d_in[17];
    const float* bn2g = (const float*)d_in[18];
    const float* bn2b = (const float*)d_in[19];
    const float* bn2m = (const float*)d_in[20];
    const float* bn2v = (const float*)d_in[21];
    float* out = (float*)d_out;

    float *pv, *pom;
    cudaGetSymbolAddress((void**)&pv,  g_v);
    cudaGetSymbolAddress((void**)&pom, g_om);
    __nv_bfloat16 *hbh, *hbl, *tbh, *tbl, *obh, *obl;
    __nv_bfloat16 *wvh, *wvl, *womh, *woml, *woh, *wol;
    cudaGetSymbolAddress((void**)&hbh, g_hb_hi); cudaGetSymbolAddress((void**)&hbl, g_hb_lo);
    cudaGetSymbolAddress((void**)&tbh, g_tb_hi); cudaGetSymbolAddress((void**)&tbl, g_tb_lo);
    cudaGetSymbolAddress((void**)&obh, g_ob_hi); cudaGetSymbolAddress((void**)&obl, g_ob_lo);
    cudaGetSymbolAddress((void**)&wvh, g_wv_hi); cudaGetSymbolAddress((void**)&wvl, g_wv_lo);
    cudaGetSymbolAddress((void**)&womh, g_wom_hi); cudaGetSymbolAddress((void**)&woml, g_wom_lo);
    cudaGetSymbolAddress((void**)&woh, g_wo_hi); cudaGetSymbolAddress((void**)&wol, g_wo_lo);

    const int smem_conv = NSTG*STGB + 1024;
    const int smem_gemm = 96*1024 + 1024;
    cudaFuncSetAttribute(conv1_mma, cudaFuncAttributeMaxDynamicSharedMemorySize, smem_conv);
    cudaFuncSetAttribute(gemm_tc<0>, cudaFuncAttributeMaxDynamicSharedMemorySize, smem_gemm);
    cudaFuncSetAttribute(gemm_tc<1>, cudaFuncAttributeMaxDynamicSharedMemorySize, smem_gemm);
    cudaFuncSetAttribute(gemm_tc<2>, cudaFuncAttributeMaxDynamicSharedMemorySize, smem_gemm);

    xprep<<<8*58, 256>>>(x);
    wprep<<<(NCHUNK*128*64 + 255)/256, 256>>>(wcv1);
    prep_wsplit<<<64, 256>>>(winp, 128, nullptr, 0, 128, wvh, wvl);
    prep_wsplit<<<64, 256>>>(woff, 72, wmsk, 36, 128, womh, woml);
    prep_wsplit<<<128, 256>>>(wout, 256, nullptr, 0, 256, woh, wol);

    conv1_mma<<<8*28, 256, smem_conv>>>(bn1g, bn1b, bn1m, bn1v);
    dw_ln_gelu<<<NPIX/4, 128>>>(wdw, bdw, lng, lnb);

    gemm_tc<0><<<dim3(NPIX/64, 1), 256, smem_gemm>>>(hbh, hbl, wvh, wvl,
        128, 128, 128, binp, nullptr, pv,
        nullptr, nullptr, nullptr, nullptr, nullptr, nullptr);
    gemm_tc<1><<<dim3(NPIX/64, 1), 256, smem_gemm>>>(tbh, tbl, womh, woml,
        128, NOM, 72, boff, bmsk, pom,
        nullptr, nullptr, nullptr, nullptr, nullptr, nullptr);
    dcn_core<<<(NPIX*GG)/8, 256>>>();
    gemm_tc<2><<<dim3(NPIX/64, 2), 256, smem_gemm>>>(obh, obl, woh, wol,
        256, 256, 256, nullptr, nullptr, out,
        bout, bn2g, bn2b, bn2m, bn2v, x);
}